// round 12
// baseline (speedup 1.0000x reference)
#include <cuda_runtime.h>

// ---------------- problem constants ----------------
constexpr int NAg = 10240;           // B*NA agents
constexpr int NE  = 10, NAL = 9;
constexpr int PEc = NAg * NE;        // 102400 enemy pairs
constexpr int PAc = NAg * NAL;       // 92160 ally pairs
constexpr int REc = 2 * PEc;         // 204800 enemy rows
constexpr int RAc = 2 * PAc;         // 184320 ally rows
constexpr int RTc = REc + RAc;       // 389120
constexpr float EPS_ = 1e-5f;

// sumsq slots (within double ss block)
constexpr int SS_E1 = 0,   SS_A1 = 64,  SS_E2 = 128, SS_A2 = 192;
constexpr int SS_F1 = 256, SS_F2 = 320;
constexpr int SS_IE1 = 384, SS_IA1 = 448, SS_IE2 = 512, SS_IA2 = 576;
constexpr int SS_IE3 = 640, SS_IA3 = 641;

// ---------------- scratch layout (floats) ----------------
constexpr size_t OFF_Y1   = 0;
constexpr size_t OFF_Y2   = OFF_Y1   + (size_t)RTc * 64;
constexpr size_t OFF_POOL = OFF_Y2   + (size_t)RTc * 64;
constexpr size_t OFF_YF1  = OFF_POOL + (size_t)NAg * 128;
constexpr size_t OFF_VF   = OFF_YF1  + (size_t)NAg * 128;
constexpr size_t OFF_SF   = OFF_VF   + (size_t)NAg * 128;
constexpr size_t OFF_VCE  = OFF_SF   + (size_t)NAg * 64;
constexpr size_t OFF_VCA  = OFF_VCE  + (size_t)NAg * 128;
constexpr size_t OFF_SFC  = OFF_VCA  + (size_t)NAg * 128;
constexpr size_t OFF_YI1E = OFF_SFC  + (size_t)NAg * 128;
constexpr size_t OFF_YI1A = OFF_YI1E + (size_t)REc * 64;
constexpr size_t OFF_YI2E = OFF_YI1A + (size_t)REc * 64;
constexpr size_t OFF_YI2A = OFF_YI2E + (size_t)REc * 64;
constexpr size_t OFF_Y3   = OFF_YI2A + (size_t)REc * 64;
constexpr size_t OFF_H1   = OFF_Y3   + (size_t)2 * REc;
constexpr size_t OFF_AQ   = OFF_H1   + (size_t)PEc * 128;   // PEc floats
constexpr size_t OFF_OAH  = OFF_AQ   + (size_t)PEc;
constexpr size_t OFF_MV   = OFF_OAH  + (size_t)NAg * 64;
constexpr size_t SCR_TOTAL = OFF_MV + 20480;

__device__ __align__(16) float g_scratch[SCR_TOTAL];
__device__ __align__(16) double g_ssd[768];

typedef unsigned long long ull;

// ---------------- packed f32x2 helpers ----------------
__device__ __forceinline__ void ffma2(ull& d, ull a, ull b) {
    asm("fma.rn.f32x2 %0, %1, %2, %0;" : "+l"(d) : "l"(a), "l"(b));
}
__device__ __forceinline__ float2 unpk(ull v) {
    float2 r; asm("mov.b64 {%0, %1}, %2;" : "=f"(r.x), "=f"(r.y) : "l"(v)); return r;
}
__device__ __forceinline__ ull dup2(float x) {
    ull d; asm("mov.b64 %0, {%1, %1};" : "=l"(d) : "f"(x)); return d;
}
__device__ __forceinline__ void stdup4(float2* row, float4 v) {
    row[0] = make_float2(v.x, v.x); row[1] = make_float2(v.y, v.y);
    row[2] = make_float2(v.z, v.z); row[3] = make_float2(v.w, v.w);
}

// ---------------- zero kernel (mv floats + ss doubles) ----------------
__global__ void zero_k(float* __restrict__ mv, double* __restrict__ ssd) {
    int i = blockIdx.x * 256 + threadIdx.x;
    if (i < 20480) mv[i] = 0.f;
    if (i < 768) ssd[i] = 0.0;
}

// ---------------- ref-exact qbn+qrelu pair op ----------------
__device__ __forceinline__ void actpair(float& a, float& b, float denom) {
    a = __fdiv_rn(a, denom);
    b = __fdiv_rn(b, denom);
    float mod = __fsqrt_rn(__fadd_rn(__fmul_rn(a, a), __fmul_rn(b, b)));
    float coeff = fminf(mod, 1.f);          // == mod/max(1,mod) exactly
    a = __fmul_rn(a, coeff);
    b = __fmul_rn(b, coeff);
}

// ---------------- layer1: build_vec (ref-exact fp32) + 19-dot + sumsq ------
__global__ void __launch_bounds__(64) layer1_k(
    const float* __restrict__ own, const float* __restrict__ efeat,
    const float* __restrict__ afeat, const float* __restrict__ We,
    const float* __restrict__ Wa, float* __restrict__ y1,
    double* __restrict__ ssd)
{
    constexpr int PPB = 32;
    constexpr int EBLK = PEc / PPB;  // 3200
    const bool isE = blockIdx.x < EBLK;
    const int pbase = (isE ? blockIdx.x : blockIdx.x - EBLK) * PPB;
    const float* W = isE ? We : Wa;
    const float* feats = isE ? efeat : afeat;
    const int nper = isE ? NE : NAL;
    const int tid = threadIdx.x;

    __shared__ float2 evp[PPB][20];   // (comp0, comp1) pairs

    if (tid < PPB) {
        int p = pbase + tid;
        const float* f = feats + (size_t)p * 9;
        const float* o = own + (size_t)(p / nper) * 11;
        float f2 = f[2], f3 = f[3];
        float pm = __fsqrt_rn(__fadd_rn(__fmul_rn(f2, f2), __fmul_rn(f3, f3)));
        bool mask = (pm == 0.f);
        float denom = mask ? 1.f : pm;
        evp[tid][0] = make_float2(f2, f3);
        float oth[7] = { f[0], f[1], f[4], f[5], f[6], f[7], f[8] };
        #pragma unroll
        for (int k = 0; k < 7; k++) {
            float om = __fsqrt_rn(__fmul_rn(2.f * oth[k], oth[k]));
            float u = mask ? 0.f : __fdiv_rn(om, denom);
            evp[tid][1 + k] = make_float2(__fmul_rn(f2, u), __fmul_rn(f3, u));
        }
        #pragma unroll
        for (int k = 0; k < 11; k++) {
            float q = __fmul_rn(o[k], o[k]);
            float om = __fsqrt_rn(__fadd_rn(q, q));
            float u = mask ? 0.f : __fdiv_rn(om, denom);
            evp[tid][8 + k] = make_float2(__fmul_rn(f2, u), __fmul_rn(f3, u));
        }
    }
    __syncthreads();

    ull wp[19];
    #pragma unroll
    for (int k = 0; k < 19; k++) wp[k] = dup2(__ldg(W + k * 64 + tid));

    float ssa = 0.f;
    size_t rowG0 = (isE ? (size_t)0 : (size_t)REc) + (size_t)pbase * 2;
    for (int j = 0; j < PPB; j++) {
        ull s01 = 0;
        #pragma unroll
        for (int k = 0; k < 19; k++)
            ffma2(s01, *reinterpret_cast<const ull*>(&evp[j][k]), wp[k]);
        float2 s = unpk(s01);
        y1[(rowG0 + 2 * j) * 64 + tid]     = s.x;
        y1[(rowG0 + 2 * j + 1) * 64 + tid] = s.y;
        ssa += s.x * s.x + s.y * s.y;
    }
    atomicAdd(ssd + (isE ? SS_E1 : SS_A1) + tid, (double)ssa);
}

// ---------------- standalone act (VF only): in-place + merge ----------------
__global__ void act_k(float* __restrict__ y, const double* __restrict__ ssd,
                      int npairs, double invN, float* __restrict__ mergeOut)
{
    __shared__ float dsh[64];
    if (threadIdx.x < 64) {
        float m = (float)(ssd[threadIdx.x] * invN);
        dsh[threadIdx.x] = __fsqrt_rn(__fadd_rn(m, EPS_));
    }
    __syncthreads();
    int idx = blockIdx.x * 256 + threadIdx.x;
    if (idx >= npairs * 64) return;
    int p = idx >> 6, c = idx & 63;
    size_t i0 = (size_t)p * 128 + c;
    float a = y[i0], b = y[i0 + 64];
    actpair(a, b, dsh[c]);
    y[i0] = a; y[i0 + 64] = b;
    if (mergeOut)
        mergeOut[(size_t)p * 64 + c] = __fadd_rn(__fmul_rn(a, a), __fmul_rn(b, b));
}

// ---------------- generic dual-region GEMM (FFMA2 inner loop) ----------------
// out = f(in) @ W (+add) (relu) ; optional column-sumsq ; optional 64->1 dot out
// ADDMODE: 0 none; 1 bias (N); 2 ar=((r>>1)/NE)*2+(r&1); 3 ar=r/NE  (r local)
// INMODE: 0 plain; 1 act-on-load (pairs, K=64); 2 merge-on-load (pairs->scalar, K=64)
template<int K, int N, int ADDMODE, bool RELU, bool WITH_SS, int INMODE, bool DOT_OUT>
__global__ void __launch_bounds__(256) gemm_k(
    int splitBlk,
    const float* __restrict__ inA, const float* __restrict__ inB,
    float* __restrict__ outA, float* __restrict__ outB,
    const float* __restrict__ WA_, const float* __restrict__ WB_,
    const float* __restrict__ addA, const float* __restrict__ addB,
    double* __restrict__ ssOutA, double* __restrict__ ssOutB,
    const double* __restrict__ ssInA, const double* __restrict__ ssInB,
    double invNA, double invNB,
    const float* __restrict__ dotw, float* __restrict__ dotOut)
{
    const int reg = (blockIdx.x >= splitBlk) ? 1 : 0;
    const int blk = blockIdx.x - reg * splitBlk;
    const float* in  = reg ? inB  : inA;
    float* out       = reg ? outB : outA;
    const float* W   = reg ? WB_  : WA_;
    const float* addp= reg ? addB : addA;
    double* ssOut    = reg ? ssOutB : ssOutA;

    constexpr int CG = N / 4;
    constexpr int RG = 256 / CG;
    constexpr int TILE_R = RG * 4;
    constexpr int XST = K + 2;                  // float2 stride (keeps 16B align)
    extern __shared__ unsigned char smem_dyn[];
    float2* xs = reinterpret_cast<float2*>(smem_dyn);   // [TILE_R][XST] dup pairs
    __shared__ float red[(WITH_SS || DOT_OUT) ? RG * N : 1];
    __shared__ float scs[(INMODE != 0) ? 64 : 1];

    const int tid = threadIdx.x;
    const int cg = tid % CG;
    const int rg = tid / CG;
    const int rowBase = blk * TILE_R;

    if (INMODE != 0) {
        const double* ssIn = reg ? ssInB : ssInA;
        double invN = reg ? invNB : invNA;
        if (tid < 64) {
            float m = (float)(ssIn[tid] * invN);
            scs[tid] = __fsqrt_rn(__fadd_rn(m, EPS_));
        }
        __syncthreads();
    }

    if (INMODE == 1) {
        // act on load: tile rows are raw rows; pair rows 2p, 2p+1 within tile
        #pragma unroll
        for (int i = tid; i < (TILE_R / 2) * 16; i += 256) {
            int pr = i >> 4, c = i & 15;
            const float* p0 = in + (size_t)(rowBase + 2 * pr) * 64 + c * 4;
            float4 v0 = __ldg((const float4*)p0);
            float4 v1 = __ldg((const float4*)(p0 + 64));
            actpair(v0.x, v1.x, scs[c * 4 + 0]);
            actpair(v0.y, v1.y, scs[c * 4 + 1]);
            actpair(v0.z, v1.z, scs[c * 4 + 2]);
            actpair(v0.w, v1.w, scs[c * 4 + 3]);
            stdup4(xs + (size_t)(2 * pr) * XST + c * 4, v0);
            stdup4(xs + (size_t)(2 * pr + 1) * XST + c * 4, v1);
        }
    } else if (INMODE == 2) {
        // merge on load: tile rows are PAIRS; xs[pr][c] = act(a)^2+act(b)^2
        #pragma unroll
        for (int i = tid; i < TILE_R * 16; i += 256) {
            int pr = i >> 4, c = i & 15;
            const float* p0 = in + (size_t)(rowBase + pr) * 128 + c * 4;
            float4 v0 = __ldg((const float4*)p0);
            float4 v1 = __ldg((const float4*)(p0 + 64));
            actpair(v0.x, v1.x, scs[c * 4 + 0]);
            actpair(v0.y, v1.y, scs[c * 4 + 1]);
            actpair(v0.z, v1.z, scs[c * 4 + 2]);
            actpair(v0.w, v1.w, scs[c * 4 + 3]);
            float4 mg;
            mg.x = __fadd_rn(__fmul_rn(v0.x, v0.x), __fmul_rn(v1.x, v1.x));
            mg.y = __fadd_rn(__fmul_rn(v0.y, v0.y), __fmul_rn(v1.y, v1.y));
            mg.z = __fadd_rn(__fmul_rn(v0.z, v0.z), __fmul_rn(v1.z, v1.z));
            mg.w = __fadd_rn(__fmul_rn(v0.w, v0.w), __fmul_rn(v1.w, v1.w));
            stdup4(xs + (size_t)pr * XST + c * 4, mg);
        }
    } else {
        constexpr int KV = K / 4;
        #pragma unroll
        for (int i = tid; i < TILE_R * KV; i += 256) {
            int r = i / KV, c = i - r * KV;
            float4 v = __ldg(reinterpret_cast<const float4*>(in + (size_t)(rowBase + r) * K) + c);
            stdup4(xs + (size_t)r * XST + c * 4, v);
        }
    }
    __syncthreads();

    ull acc2[4][2] = {};
    const longlong2* Wv = reinterpret_cast<const longlong2*>(W);
    const int r4 = rg * 4;
    #pragma unroll 4
    for (int k0 = 0; k0 < K; k0 += 2) {
        ull a0[4], a1[4];
        #pragma unroll
        for (int i = 0; i < 4; i++) {
            longlong2 t = *reinterpret_cast<const longlong2*>(xs + (size_t)(r4 + i) * XST + k0);
            a0[i] = (ull)t.x; a1[i] = (ull)t.y;
        }
        longlong2 b0 = __ldg(Wv + (size_t)k0 * (N / 4) + cg);
        longlong2 b1 = __ldg(Wv + (size_t)(k0 + 1) * (N / 4) + cg);
        #pragma unroll
        for (int i = 0; i < 4; i++) {
            ffma2(acc2[i][0], a0[i], (ull)b0.x);
            ffma2(acc2[i][1], a0[i], (ull)b0.y);
            ffma2(acc2[i][0], a1[i], (ull)b1.x);
            ffma2(acc2[i][1], a1[i], (ull)b1.y);
        }
    }

    float4 dw = make_float4(0.f, 0.f, 0.f, 0.f);
    if (DOT_OUT) dw = __ldg(reinterpret_cast<const float4*>(dotw) + cg);

    float ssl[4] = {0.f, 0.f, 0.f, 0.f};
    #pragma unroll
    for (int i = 0; i < 4; i++) {
        int r = rowBase + r4 + i;
        float2 lo = unpk(acc2[i][0]);
        float2 hi = unpk(acc2[i][1]);
        float4 a = make_float4(lo.x, lo.y, hi.x, hi.y);
        if (ADDMODE == 1) {
            float4 bb = __ldg(reinterpret_cast<const float4*>(addp) + cg);
            a.x += bb.x; a.y += bb.y; a.z += bb.z; a.w += bb.w;
        } else if (ADDMODE == 2) {
            int ar = ((r >> 1) / NE) * 2 + (r & 1);
            float4 bb = __ldg(reinterpret_cast<const float4*>(addp + (size_t)ar * N) + cg);
            a.x += bb.x; a.y += bb.y; a.z += bb.z; a.w += bb.w;
        } else if (ADDMODE == 3) {
            int ar = r / NE;
            float4 bb = __ldg(reinterpret_cast<const float4*>(addp + (size_t)ar * N) + cg);
            a.x += bb.x; a.y += bb.y; a.z += bb.z; a.w += bb.w;
        }
        if (WITH_SS) {
            ssl[0] += a.x * a.x; ssl[1] += a.y * a.y;
            ssl[2] += a.z * a.z; ssl[3] += a.w * a.w;
        }
        if (RELU) {
            a.x = fmaxf(a.x, 0.f); a.y = fmaxf(a.y, 0.f);
            a.z = fmaxf(a.z, 0.f); a.w = fmaxf(a.w, 0.f);
        }
        if (DOT_OUT) {
            red[(r4 + i) * CG + cg] = a.x * dw.x + a.y * dw.y + a.z * dw.z + a.w * dw.w;
        } else {
            *(reinterpret_cast<float4*>(out + (size_t)r * N) + cg) = a;
        }
    }

    if (DOT_OUT) {
        __syncthreads();
        if (tid < TILE_R) {
            float s = 0.f;
            #pragma unroll
            for (int g = 0; g < CG; g++) s += red[tid * CG + g];
            dotOut[rowBase + tid] = s;
        }
    }
    if (WITH_SS) {
        *reinterpret_cast<float4*>(&red[rg * N + cg * 4]) =
            make_float4(ssl[0], ssl[1], ssl[2], ssl[3]);
        __syncthreads();
        if (tid < N) {
            float s = 0.f;
            #pragma unroll
            for (int g = 0; g < RG; g++) s += red[g * N + tid];
            atomicAdd(ssOut + tid, (double)s);
        }
    }
}

// ---------------- paired-weight GEMM (IE1+IA1, FFMA2) ----------------
__global__ void __launch_bounds__(256) gemmpair_k(
    const float* __restrict__ in,               // raw Y2-E
    const float* __restrict__ WE_, const float* __restrict__ WA_,
    const float* __restrict__ addE, const float* __restrict__ addA,
    float* __restrict__ outE, float* __restrict__ outA,
    double* __restrict__ ssE, double* __restrict__ ssA,
    const double* __restrict__ ssIn, double invN)
{
    constexpr int TILE_R = 32;
    constexpr int XST = 66;
    __shared__ float2 xs[TILE_R * XST];
    __shared__ float red[8 * 128];
    __shared__ float scs[64];

    const int tid = threadIdx.x;
    const int cg = tid % 32;
    const int rg = tid / 32;
    const int half = cg >> 4;
    const int ch = cg & 15;
    const int rowBase = blockIdx.x * TILE_R;

    if (tid < 64) {
        float m = (float)(ssIn[tid] * invN);
        scs[tid] = __fsqrt_rn(__fadd_rn(m, EPS_));
    }
    __syncthreads();

    {
        int i = tid;
        int pr = i >> 4, c = i & 15;
        const float* p0 = in + (size_t)(rowBase + 2 * pr) * 64 + c * 4;
        float4 v0 = __ldg((const float4*)p0);
        float4 v1 = __ldg((const float4*)(p0 + 64));
        actpair(v0.x, v1.x, scs[c * 4 + 0]);
        actpair(v0.y, v1.y, scs[c * 4 + 1]);
        actpair(v0.z, v1.z, scs[c * 4 + 2]);
        actpair(v0.w, v1.w, scs[c * 4 + 3]);
        stdup4(xs + (size_t)(2 * pr) * XST + c * 4, v0);
        stdup4(xs + (size_t)(2 * pr + 1) * XST + c * 4, v1);
    }
    __syncthreads();

    ull acc2[4][2] = {};
    const longlong2* Wv = reinterpret_cast<const longlong2*>(half ? WA_ : WE_);
    const int r4 = rg * 4;
    #pragma unroll 4
    for (int k0 = 0; k0 < 64; k0 += 2) {
        ull a0[4], a1[4];
        #pragma unroll
        for (int i = 0; i < 4; i++) {
            longlong2 t = *reinterpret_cast<const longlong2*>(xs + (size_t)(r4 + i) * XST + k0);
            a0[i] = (ull)t.x; a1[i] = (ull)t.y;
        }
        longlong2 b0 = __ldg(Wv + (size_t)k0 * 16 + ch);
        longlong2 b1 = __ldg(Wv + (size_t)(k0 + 1) * 16 + ch);
        #pragma unroll
        for (int i = 0; i < 4; i++) {
            ffma2(acc2[i][0], a0[i], (ull)b0.x);
            ffma2(acc2[i][1], a0[i], (ull)b0.y);
            ffma2(acc2[i][0], a1[i], (ull)b1.x);
            ffma2(acc2[i][1], a1[i], (ull)b1.y);
        }
    }

    const float* addp = half ? addA : addE;
    float* out = half ? outA : outE;
    float ssl[4] = {0.f, 0.f, 0.f, 0.f};
    #pragma unroll
    for (int i = 0; i < 4; i++) {
        int r = rowBase + r4 + i;
        float2 lo = unpk(acc2[i][0]);
        float2 hi = unpk(acc2[i][1]);
        float4 a = make_float4(lo.x, lo.y, hi.x, hi.y);
        int ar = ((r >> 1) / NE) * 2 + (r & 1);
        float4 bb = __ldg(reinterpret_cast<const float4*>(addp + (size_t)ar * 64) + ch);
        a.x += bb.x; a.y += bb.y; a.z += bb.z; a.w += bb.w;
        ssl[0] += a.x * a.x; ssl[1] += a.y * a.y;
        ssl[2] += a.z * a.z; ssl[3] += a.w * a.w;
        *(reinterpret_cast<float4*>(out + (size_t)r * 64) + ch) = a;
    }

    *reinterpret_cast<float4*>(&red[rg * 128 + cg * 4]) =
        make_float4(ssl[0], ssl[1], ssl[2], ssl[3]);
    __syncthreads();
    if (tid < 128) {
        float s = 0.f;
        #pragma unroll
        for (int g = 0; g < 8; g++) s += red[g * 128 + tid];
        atomicAdd((tid < 64 ? ssE + tid : ssA + tid - 64), (double)s);
    }
}

// ---------------- fused qmaxpool: act applied inline on raw Y2 -------------
__global__ void maxpoolf_k(const float* __restrict__ y2E,
                           const float* __restrict__ y2A,
                           const double* __restrict__ ssd,
                           float* __restrict__ pool)
{
    __shared__ float dE[64], dA[64];
    if (threadIdx.x < 64) {
        float mE = (float)(ssd[SS_E2 + threadIdx.x] * (1.0 / REc));
        dE[threadIdx.x] = __fsqrt_rn(__fadd_rn(mE, EPS_));
        float mA = (float)(ssd[SS_A2 + threadIdx.x] * (1.0 / RAc));
        dA[threadIdx.x] = __fsqrt_rn(__fadd_rn(mA, EPS_));
    }
    __syncthreads();
    int idx = blockIdx.x * 256 + threadIdx.x;
    if (idx >= NAg * 64) return;
    int agent = idx >> 6, c = idx & 63;
    float best = -1.f, b0 = 0.f, b1 = 0.f;
    float de = dE[c], da = dA[c];
    #pragma unroll
    for (int e = 0; e < NE; e++) {
        size_t r = ((size_t)(agent * NE + e)) * 128 + c;
        float v0 = __ldg(y2E + r), v1 = __ldg(y2E + r + 64);
        actpair(v0, v1, de);
        float m = __fadd_rn(__fmul_rn(v0, v0), __fmul_rn(v1, v1));
        if (m > best) { best = m; b0 = v0; b1 = v1; }
    }
    #pragma unroll
    for (int e = 0; e < NAL; e++) {
        size_t r = ((size_t)(agent * NAL + e)) * 128 + c;
        float v0 = __ldg(y2A + r), v1 = __ldg(y2A + r + 64);
        actpair(v0, v1, da);
        float m = __fadd_rn(__fmul_rn(v0, v0), __fmul_rn(v1, v1));
        if (m > best) { best = m; b0 = v0; b1 = v1; }
    }
    pool[(size_t)agent * 128 + c] = b0;
    pool[(size_t)agent * 128 + 64 + c] = b1;
}

// ---------------- imp3: fused act + 64->1 dot per pair + scalar sumsq ------
__global__ void __launch_bounds__(256) imp3f_k(
    const float* __restrict__ yi2,
    const float* __restrict__ wE, const float* __restrict__ wA,
    float* __restrict__ y3, double* __restrict__ ssd)
{
    constexpr int EBLK = PEc / 256;  // 400
    const int reg = (blockIdx.x >= EBLK) ? 1 : 0;
    const int pl = (blockIdx.x - reg * EBLK) * 256 + threadIdx.x;

    __shared__ float rcs[64];
    if (threadIdx.x < 64) {
        float m = (float)(ssd[(reg ? SS_IA2 : SS_IE2) + threadIdx.x] * (1.0 / REc));
        rcs[threadIdx.x] = __fsqrt_rn(__fadd_rn(m, EPS_));
    }
    __syncthreads();

    int gp = reg ? (PEc + pl) : pl;
    const float* src = yi2 + (size_t)(2 * gp) * 64;
    const float* w = reg ? wA : wE;

    float s0 = 0.f, s1 = 0.f;
    #pragma unroll
    for (int k4 = 0; k4 < 16; k4++) {
        float4 v0 = __ldg(reinterpret_cast<const float4*>(src) + k4);
        float4 v1 = __ldg(reinterpret_cast<const float4*>(src + 64) + k4);
        float4 dn = *reinterpret_cast<const float4*>(&rcs[k4 * 4]);
        float4 wv = __ldg(reinterpret_cast<const float4*>(w) + k4);
        #pragma unroll
        for (int j = 0; j < 4; j++) {
            float a = ((const float*)&v0)[j];
            float b = ((const float*)&v1)[j];
            actpair(a, b, ((const float*)&dn)[j]);
            float ww = ((const float*)&wv)[j];
            s0 = fmaf(a, ww, s0);
            s1 = fmaf(b, ww, s1);
        }
    }
    y3[2 * gp] = s0;
    y3[2 * gp + 1] = s1;

    __shared__ float red[256];
    red[threadIdx.x] = s0 * s0 + s1 * s1;
    __syncthreads();
    for (int o = 128; o > 0; o >>= 1) {
        if (threadIdx.x < o) red[threadIdx.x] += red[threadIdx.x + o];
        __syncthreads();
    }
    if (threadIdx.x == 0) atomicAdd(ssd + (reg ? SS_IA3 : SS_IE3), (double)red[0]);
}

// ---------------- move_vec accumulation ----------------
__global__ void mv_k(const float* __restrict__ y3, const double* __restrict__ ssd,
                     float* __restrict__ mv)
{
    int idx = blockIdx.x * blockDim.x + threadIdx.x;
    if (idx >= 2 * PEc) return;
    bool isE = idx < PEc;
    int p = isE ? idx : idx - PEc;
    float m = (float)(ssd[isE ? SS_IE3 : SS_IA3] * (1.0 / REc));
    float denom = __fsqrt_rn(__fadd_rn(m, EPS_));
    size_t base = (isE ? (size_t)0 : (size_t)REc) + (size_t)p * 2;
    float b0 = __fdiv_rn(y3[base], denom);
    float b1 = __fdiv_rn(y3[base + 1], denom);
    float mod = __fsqrt_rn(__fadd_rn(__fmul_rn(b0, b0), __fmul_rn(b1, b1)));
    float coeff = fminf(mod, 1.f);
    int agent = p / NE;
    atomicAdd(mv + agent * 2,     __fmul_rn(b0, coeff));
    atomicAdd(mv + agent * 2 + 1, __fmul_rn(b1, coeff));
}

// ---------------- final assembly ----------------
__device__ __forceinline__ float wred(float v) {
    #pragma unroll
    for (int o = 16; o; o >>= 1) v += __shfl_xor_sync(0xffffffffu, v, o);
    return v;
}

__global__ void __launch_bounds__(256) final_k(
    const float* __restrict__ oah, const float* __restrict__ Woa2,
    const float* __restrict__ boa2,
    const float* __restrict__ aqbuf, const float* __restrict__ bat3,
    const float* __restrict__ mv, float* __restrict__ out)
{
    int agent = blockIdx.x * 8 + (threadIdx.x >> 5);
    int lane = threadIdx.x & 31;
    const float* oa = oah + (size_t)agent * 64;
    float o0 = oa[2 * lane], o1 = oa[2 * lane + 1];
    float q[3];
    #pragma unroll
    for (int j = 0; j < 3; j++) {
        float part = o0 * __ldg(Woa2 + (2 * lane) * 3 + j)
                   + o1 * __ldg(Woa2 + (2 * lane + 1) * 3 + j);
        q[j] = wred(part);
    }
    float* o = out + (size_t)agent * 16;
    if (lane == 0) {
        float q2 = q[2] + boa2[2];
        float m0 = mv[agent * 2], m1 = mv[agent * 2 + 1];
        o[0] = q[0] + boa2[0];
        o[1] = q[1] + boa2[1];
        o[2] = q2 + m1;
        o[3] = q2 - m1;
        o[4] = q2 + m0;
        o[5] = q2 - m0;
    }
    if (lane < NE)
        o[6 + lane] = aqbuf[(size_t)agent * NE + lane] + bat3[0];
}

// ---------------- launcher ----------------
extern "C" void kernel_launch(void* const* d_in, const int* in_sizes, int n_in,
                              void* d_out, int out_size)
{
    const float* own   = (const float*)d_in[0];
    const float* ef    = (const float*)d_in[1];
    const float* af    = (const float*)d_in[2];
    const float* W_e1  = (const float*)d_in[3];
    const float* W_e2  = (const float*)d_in[4];
    const float* W_a1  = (const float*)d_in[5];
    const float* W_a2  = (const float*)d_in[6];
    const float* W_f1  = (const float*)d_in[7];
    const float* W_f2  = (const float*)d_in[8];
    const float* W_ie1 = (const float*)d_in[9];
    const float* W_ie2 = (const float*)d_in[10];
    const float* W_ie3 = (const float*)d_in[11];
    const float* W_ia1 = (const float*)d_in[12];
    const float* W_ia2 = (const float*)d_in[13];
    const float* W_ia3 = (const float*)d_in[14];
    const float* W_oa1 = (const float*)d_in[15];
    const float* b_oa1 = (const float*)d_in[16];
    const float* W_oa2 = (const float*)d_in[17];
    const float* b_oa2 = (const float*)d_in[18];
    const float* W_at1 = (const float*)d_in[19];
    const float* b_at1 = (const float*)d_in[20];
    const float* W_at2 = (const float*)d_in[21];
    const float* b_at2 = (const float*)d_in[22];
    const float* W_at3 = (const float*)d_in[23];
    const float* b_at3 = (const float*)d_in[24];
    float* out = (float*)d_out;

    float* S = nullptr;
    cudaGetSymbolAddress((void**)&S, g_scratch);
    double* ssd = nullptr;
    cudaGetSymbolAddress((void**)&ssd, g_ssd);

    // dynamic smem sizes: TILE_R*(K+2)*sizeof(float2)
    constexpr int SM_K64N64  = 64 * 66 * 8;    // 33792
    constexpr int SM_K64N128 = 32 * 66 * 8;    // 16896
    constexpr int SM_K128N64 = 64 * 130 * 8;   // 66560 (> 48KB default)
    cudaFuncSetAttribute(gemm_k<128, 64, 1, true, false, 0, true>,
                         cudaFuncAttributeMaxDynamicSharedMemorySize, SM_K128N64);

    zero_k<<<80, 256>>>(S + OFF_MV, ssd);

    // layer 1 (ref-exact build_vec + W_e1/W_a1), raw output + ss E1/A1
    layer1_k<<<(PEc + PAc) / 32, 64>>>(own, ef, af, W_e1, W_a1, S + OFF_Y1, ssd);

    // layer 2, dual region, act(Y1) fused on load, ss E2/A2 (Y2 stays RAW)
    gemm_k<64, 64, 0, false, true, 1, false><<<RTc / 64, 256, SM_K64N64>>>(
        REc / 64,
        S + OFF_Y1, S + OFF_Y1 + (size_t)REc * 64,
        S + OFF_Y2, S + OFF_Y2 + (size_t)REc * 64,
        W_e2, W_a2, nullptr, nullptr,
        ssd + SS_E2, ssd + SS_A2,
        ssd + SS_E1, ssd + SS_A1, 1.0 / REc, 1.0 / RAc,
        nullptr, nullptr);

    // fused act + qmaxpool on raw Y2
    maxpoolf_k<<<(NAg * 64) / 256, 256>>>(S + OFF_Y2, S + OFF_Y2 + (size_t)REc * 64,
                                          ssd, S + OFF_POOL);
    gemm_k<64, 64, 0, false, true, 0, false><<<(2 * NAg) / 64, 256, SM_K64N64>>>(
        (2 * NAg) / 64, S + OFF_POOL, S + OFF_POOL, S + OFF_YF1, S + OFF_YF1,
        W_f1, W_f1, nullptr, nullptr, ssd + SS_F1, ssd + SS_F1,
        nullptr, nullptr, 0.0, 0.0, nullptr, nullptr);
    gemm_k<64, 64, 0, false, true, 1, false><<<(2 * NAg) / 64, 256, SM_K64N64>>>(
        (2 * NAg) / 64, S + OFF_YF1, S + OFF_YF1, S + OFF_VF, S + OFF_VF,
        W_f2, W_f2, nullptr, nullptr, ssd + SS_F2, ssd + SS_F2,
        ssd + SS_F1, ssd + SS_F1, 1.0 / (2 * NAg), 1.0 / (2 * NAg), nullptr, nullptr);
    act_k<<<(NAg * 64) / 256, 256>>>(S + OFF_VF, ssd + SS_F2, NAg, 1.0 / (2 * NAg), S + OFF_SF);

    // vf @ top-half of W_ie1 / W_ia1 (dual; VF act'd in place)
    gemm_k<64, 64, 0, false, false, 0, false><<<2 * ((2 * NAg) / 64), 256, SM_K64N64>>>(
        (2 * NAg) / 64, S + OFF_VF, S + OFF_VF, S + OFF_VCE, S + OFF_VCA,
        W_ie1, W_ia1, nullptr, nullptr, nullptr, nullptr,
        nullptr, nullptr, 0.0, 0.0, nullptr, nullptr);

    // importance layer 1: PAIRED kernel (one pass over raw Y2-E, act on load)
    gemmpair_k<<<REc / 32, 256>>>(
        S + OFF_Y2, W_ie1 + 64 * 64, W_ia1 + 64 * 64,
        S + OFF_VCE, S + OFF_VCA,
        S + OFF_YI1E, S + OFF_YI1A,
        ssd + SS_IE1, ssd + SS_IA1,
        ssd + SS_E2, 1.0 / REc);

    // importance layer 2 (dual, act fused on load), ss IE2/IA2
    gemm_k<64, 64, 0, false, true, 1, false><<<2 * (REc / 64), 256, SM_K64N64>>>(
        REc / 64, S + OFF_YI1E, S + OFF_YI1A, S + OFF_YI2E, S + OFF_YI2A,
        W_ie2, W_ia2, nullptr, nullptr,
        ssd + SS_IE2, ssd + SS_IA2,
        ssd + SS_IE1, ssd + SS_IA1, 1.0 / REc, 1.0 / REc, nullptr, nullptr);

    // importance layer 3 (act fused) + move vec — BOTH regions PEc pairs
    imp3f_k<<<2 * (PEc / 256), 256>>>(S + OFF_YI2E, W_ie3, W_ia3, S + OFF_Y3, ssd);
    mv_k<<<(2 * PEc + 255) / 256, 256>>>(S + OFF_Y3, ssd, S + OFF_MV);

    // oaq hidden
    gemm_k<64, 64, 1, true, false, 0, false><<<NAg / 64, 256, SM_K64N64>>>(
        NAg / 64, S + OFF_SF, S + OFF_SF, S + OFF_OAH, S + OFF_OAH,
        W_oa1, W_oa1, b_oa1, b_oa1, nullptr, nullptr,
        nullptr, nullptr, 0.0, 0.0, nullptr, nullptr);

    // attention head: sf@W_at1_top + bias (per agent)
    gemm_k<64, 128, 1, false, false, 0, false><<<NAg / 32, 256, SM_K64N128>>>(
        NAg / 32, S + OFF_SF, S + OFF_SF, S + OFF_SFC, S + OFF_SFC,
        W_at1, W_at1, b_at1, b_at1, nullptr, nullptr,
        nullptr, nullptr, 0.0, 0.0, nullptr, nullptr);
    // H1 = relu(e_scalar@W_at1_bot + SFC[agent]) — e_scalar computed on load
    gemm_k<64, 128, 3, true, false, 2, false><<<PEc / 32, 256, SM_K64N128>>>(
        PEc / 32, S + OFF_Y2, S + OFF_Y2, S + OFF_H1, S + OFF_H1,
        W_at1 + 64 * 128, W_at1 + 64 * 128, S + OFF_SFC, S + OFF_SFC,
        nullptr, nullptr, ssd + SS_E2, ssd + SS_E2, 1.0 / REc, 1.0 / REc,
        nullptr, nullptr);
    // H2 with fused W_at3 dot -> aq
    gemm_k<128, 64, 1, true, false, 0, true><<<PEc / 64, 256, SM_K128N64>>>(
        PEc / 64, S + OFF_H1, S + OFF_H1, nullptr, nullptr,
        W_at2, W_at2, b_at2, b_at2, nullptr, nullptr,
        nullptr, nullptr, 0.0, 0.0, W_at3, S + OFF_AQ);

    final_k<<<NAg / 8, 256>>>(S + OFF_OAH, W_oa2, b_oa2, S + OFF_AQ, b_at3, S + OFF_MV, out);

    (void)in_sizes; (void)n_in; (void)out_size;
}

// round 13
// speedup vs baseline: 1.0785x; 1.0785x over previous
#include <cuda_runtime.h>

// ---------------- problem constants ----------------
constexpr int NAg = 10240;           // B*NA agents
constexpr int NE  = 10, NAL = 9;
constexpr int PEc = NAg * NE;        // 102400 enemy pairs
constexpr int PAc = NAg * NAL;       // 92160 ally pairs
constexpr int REc = 2 * PEc;         // 204800 enemy rows
constexpr int RAc = 2 * PAc;         // 184320 ally rows
constexpr int RTc = REc + RAc;       // 389120
constexpr float EPS_ = 1e-5f;

// sumsq slots (within double ss block)
constexpr int SS_E1 = 0,   SS_A1 = 64,  SS_E2 = 128, SS_A2 = 192;
constexpr int SS_F1 = 256, SS_F2 = 320;
constexpr int SS_IE1 = 384, SS_IA1 = 448, SS_IE2 = 512, SS_IA2 = 576;
constexpr int SS_IE3 = 640, SS_IA3 = 641;

// ---------------- scratch layout (floats) ----------------
constexpr size_t OFF_Y1   = 0;
constexpr size_t OFF_Y2   = OFF_Y1   + (size_t)RTc * 64;
constexpr size_t OFF_POOL = OFF_Y2   + (size_t)RTc * 64;
constexpr size_t OFF_YF1  = OFF_POOL + (size_t)NAg * 128;
constexpr size_t OFF_VF   = OFF_YF1  + (size_t)NAg * 128;
constexpr size_t OFF_SF   = OFF_VF   + (size_t)NAg * 128;
constexpr size_t OFF_VCE  = OFF_SF   + (size_t)NAg * 64;
constexpr size_t OFF_VCA  = OFF_VCE  + (size_t)NAg * 128;
constexpr size_t OFF_SFC  = OFF_VCA  + (size_t)NAg * 128;
constexpr size_t OFF_YI1E = OFF_SFC  + (size_t)NAg * 128;
constexpr size_t OFF_YI1A = OFF_YI1E + (size_t)REc * 64;
constexpr size_t OFF_YI2E = OFF_YI1A + (size_t)REc * 64;
constexpr size_t OFF_YI2A = OFF_YI2E + (size_t)REc * 64;
constexpr size_t OFF_Y3   = OFF_YI2A + (size_t)REc * 64;
constexpr size_t OFF_H1   = OFF_Y3   + (size_t)2 * REc;
constexpr size_t OFF_AQ   = OFF_H1   + (size_t)PEc * 128;   // PEc floats
constexpr size_t OFF_OAH  = OFF_AQ   + (size_t)PEc;
constexpr size_t OFF_MV   = OFF_OAH  + (size_t)NAg * 64;
constexpr size_t SCR_TOTAL = OFF_MV + 20480;

__device__ __align__(16) float g_scratch[SCR_TOTAL];
__device__ __align__(16) double g_ssd[768];

// ---------------- zero kernel (mv floats + ss doubles) ----------------
__global__ void zero_k(float* __restrict__ mv, double* __restrict__ ssd) {
    int i = blockIdx.x * 256 + threadIdx.x;
    if (i < 20480) mv[i] = 0.f;
    if (i < 768) ssd[i] = 0.0;
}

// ---------------- ref-exact qbn+qrelu pair op ----------------
__device__ __forceinline__ void actpair(float& a, float& b, float denom) {
    a = __fdiv_rn(a, denom);
    b = __fdiv_rn(b, denom);
    float mod = __fsqrt_rn(__fadd_rn(__fmul_rn(a, a), __fmul_rn(b, b)));
    float coeff = fminf(mod, 1.f);          // == mod/max(1,mod) exactly
    a = __fmul_rn(a, coeff);
    b = __fmul_rn(b, coeff);
}

// ---------------- layer1: build_vec (ref-exact fp32) + 19-dot + sumsq ------
__global__ void __launch_bounds__(64) layer1_k(
    const float* __restrict__ own, const float* __restrict__ efeat,
    const float* __restrict__ afeat, const float* __restrict__ We,
    const float* __restrict__ Wa, float* __restrict__ y1,
    double* __restrict__ ssd)
{
    constexpr int PPB = 32;
    constexpr int EBLK = PEc / PPB;  // 3200
    const bool isE = blockIdx.x < EBLK;
    const int pbase = (isE ? blockIdx.x : blockIdx.x - EBLK) * PPB;
    const float* W = isE ? We : Wa;
    const float* feats = isE ? efeat : afeat;
    const int nper = isE ? NE : NAL;
    const int tid = threadIdx.x;

    __shared__ float ev0[PPB][20];
    __shared__ float ev1[PPB][20];

    if (tid < PPB) {
        int p = pbase + tid;
        const float* f = feats + (size_t)p * 9;
        const float* o = own + (size_t)(p / nper) * 11;
        float f2 = f[2], f3 = f[3];
        float pm = __fsqrt_rn(__fadd_rn(__fmul_rn(f2, f2), __fmul_rn(f3, f3)));
        bool mask = (pm == 0.f);
        float denom = mask ? 1.f : pm;
        ev0[tid][0] = f2; ev1[tid][0] = f3;
        float oth[7] = { f[0], f[1], f[4], f[5], f[6], f[7], f[8] };
        #pragma unroll
        for (int k = 0; k < 7; k++) {
            float om = __fsqrt_rn(__fmul_rn(2.f * oth[k], oth[k]));
            float u = mask ? 0.f : __fdiv_rn(om, denom);
            ev0[tid][1 + k] = __fmul_rn(f2, u);
            ev1[tid][1 + k] = __fmul_rn(f3, u);
        }
        #pragma unroll
        for (int k = 0; k < 11; k++) {
            float q = __fmul_rn(o[k], o[k]);
            float om = __fsqrt_rn(__fadd_rn(q, q));
            float u = mask ? 0.f : __fdiv_rn(om, denom);
            ev0[tid][8 + k] = __fmul_rn(f2, u);
            ev1[tid][8 + k] = __fmul_rn(f3, u);
        }
    }
    __syncthreads();

    float wr[19];
    #pragma unroll
    for (int k = 0; k < 19; k++) wr[k] = __ldg(W + k * 64 + tid);

    float ssa = 0.f;
    size_t rowG0 = (isE ? (size_t)0 : (size_t)REc) + (size_t)pbase * 2;
    for (int j = 0; j < PPB; j++) {
        float s0 = 0.f, s1 = 0.f;
        #pragma unroll
        for (int k = 0; k < 19; k++) {
            s0 = fmaf(ev0[j][k], wr[k], s0);
            s1 = fmaf(ev1[j][k], wr[k], s1);
        }
        y1[(rowG0 + 2 * j) * 64 + tid]     = s0;
        y1[(rowG0 + 2 * j + 1) * 64 + tid] = s1;
        ssa += s0 * s0 + s1 * s1;
    }
    atomicAdd(ssd + (isE ? SS_E1 : SS_A1) + tid, (double)ssa);
}

// ---------------- standalone act (VF only): in-place + merge ----------------
__global__ void act_k(float* __restrict__ y, const double* __restrict__ ssd,
                      int npairs, double invN, float* __restrict__ mergeOut)
{
    __shared__ float dsh[64];
    if (threadIdx.x < 64) {
        float m = (float)(ssd[threadIdx.x] * invN);
        dsh[threadIdx.x] = __fsqrt_rn(__fadd_rn(m, EPS_));
    }
    __syncthreads();
    int idx = blockIdx.x * 256 + threadIdx.x;
    if (idx >= npairs * 64) return;
    int p = idx >> 6, c = idx & 63;
    size_t i0 = (size_t)p * 128 + c;
    float a = y[i0], b = y[i0 + 64];
    actpair(a, b, dsh[c]);
    y[i0] = a; y[i0 + 64] = b;
    if (mergeOut)
        mergeOut[(size_t)p * 64 + c] = __fadd_rn(__fmul_rn(a, a), __fmul_rn(b, b));
}

// ---------------- generic dual-region GEMM (scalar FFMA core) ----------------
// out = f(in) @ W (+add) (relu) ; optional column-sumsq ; optional 64->1 dot out
// ADDMODE: 0 none; 1 bias (N); 2 ar=((r>>1)/NE)*2+(r&1); 3 ar=r/NE  (r local)
// INMODE: 0 plain; 1 act-on-load (pairs, K=64); 2 merge-on-load (pairs->scalar, K=64)
template<int K, int N, int ADDMODE, bool RELU, bool WITH_SS, int INMODE, bool DOT_OUT>
__global__ void __launch_bounds__(256) gemm_k(
    int splitBlk,
    const float* __restrict__ inA, const float* __restrict__ inB,
    float* __restrict__ outA, float* __restrict__ outB,
    const float* __restrict__ WA_, const float* __restrict__ WB_,
    const float* __restrict__ addA, const float* __restrict__ addB,
    double* __restrict__ ssOutA, double* __restrict__ ssOutB,
    const double* __restrict__ ssInA, const double* __restrict__ ssInB,
    double invNA, double invNB,
    const float* __restrict__ dotw, float* __restrict__ dotOut)
{
    const int reg = (blockIdx.x >= splitBlk) ? 1 : 0;
    const int blk = blockIdx.x - reg * splitBlk;
    const float* in  = reg ? inB  : inA;
    float* out       = reg ? outB : outA;
    const float* W   = reg ? WB_  : WA_;
    const float* addp= reg ? addB : addA;
    double* ssOut    = reg ? ssOutB : ssOutA;

    constexpr int CG = N / 4;
    constexpr int RG = 256 / CG;
    constexpr int TILE_R = RG * 4;
    __shared__ float xs[TILE_R][K + 4];
    __shared__ float red[(WITH_SS || DOT_OUT) ? RG * N : 1];
    __shared__ float scs[(INMODE != 0) ? 64 : 1];

    const int tid = threadIdx.x;
    const int cg = tid % CG;
    const int rg = tid / CG;
    const int rowBase = blk * TILE_R;

    if (INMODE != 0) {
        const double* ssIn = reg ? ssInB : ssInA;
        double invN = reg ? invNB : invNA;
        if (tid < 64) {
            float m = (float)(ssIn[tid] * invN);
            scs[tid] = __fsqrt_rn(__fadd_rn(m, EPS_));
        }
        __syncthreads();
    }

    if (INMODE == 1) {
        // act on load: tile rows are raw rows; pair rows 2p, 2p+1 within tile
        #pragma unroll
        for (int i = tid; i < (TILE_R / 2) * 16; i += 256) {
            int pr = i >> 4, c = i & 15;
            const float* p0 = in + (size_t)(rowBase + 2 * pr) * 64 + c * 4;
            float4 v0 = __ldg((const float4*)p0);
            float4 v1 = __ldg((const float4*)(p0 + 64));
            actpair(v0.x, v1.x, scs[c * 4 + 0]);
            actpair(v0.y, v1.y, scs[c * 4 + 1]);
            actpair(v0.z, v1.z, scs[c * 4 + 2]);
            actpair(v0.w, v1.w, scs[c * 4 + 3]);
            *reinterpret_cast<float4*>(&xs[2 * pr][c * 4])     = v0;
            *reinterpret_cast<float4*>(&xs[2 * pr + 1][c * 4]) = v1;
        }
    } else if (INMODE == 2) {
        // merge on load: tile rows are PAIRS; xs[pr][c] = act(a)^2+act(b)^2
        #pragma unroll
        for (int i = tid; i < TILE_R * 16; i += 256) {
            int pr = i >> 4, c = i & 15;
            const float* p0 = in + (size_t)(rowBase + pr) * 128 + c * 4;
            float4 v0 = __ldg((const float4*)p0);
            float4 v1 = __ldg((const float4*)(p0 + 64));
            actpair(v0.x, v1.x, scs[c * 4 + 0]);
            actpair(v0.y, v1.y, scs[c * 4 + 1]);
            actpair(v0.z, v1.z, scs[c * 4 + 2]);
            actpair(v0.w, v1.w, scs[c * 4 + 3]);
            float4 mg;
            mg.x = __fadd_rn(__fmul_rn(v0.x, v0.x), __fmul_rn(v1.x, v1.x));
            mg.y = __fadd_rn(__fmul_rn(v0.y, v0.y), __fmul_rn(v1.y, v1.y));
            mg.z = __fadd_rn(__fmul_rn(v0.z, v0.z), __fmul_rn(v1.z, v1.z));
            mg.w = __fadd_rn(__fmul_rn(v0.w, v0.w), __fmul_rn(v1.w, v1.w));
            *reinterpret_cast<float4*>(&xs[pr][c * 4]) = mg;
        }
    } else {
        constexpr int KV = K / 4;
        #pragma unroll
        for (int i = tid; i < TILE_R * KV; i += 256) {
            int r = i / KV, c = i - r * KV;
            float4 v = __ldg(reinterpret_cast<const float4*>(in + (size_t)(rowBase + r) * K) + c);
            *reinterpret_cast<float4*>(&xs[r][c * 4]) = v;
        }
    }
    __syncthreads();

    float acc[4][4];
    #pragma unroll
    for (int i = 0; i < 4; i++)
        #pragma unroll
        for (int j = 0; j < 4; j++) acc[i][j] = 0.f;

    const float4* Wv = reinterpret_cast<const float4*>(W);
    const int r4 = rg * 4;
    #pragma unroll 2
    for (int k0 = 0; k0 < K; k0 += 4) {
        float xa[4][4];
        #pragma unroll
        for (int i = 0; i < 4; i++)
            *reinterpret_cast<float4*>(xa[i]) = *reinterpret_cast<const float4*>(&xs[r4 + i][k0]);
        #pragma unroll
        for (int kk = 0; kk < 4; kk++) {
            float4 b = __ldg(Wv + (k0 + kk) * CG + cg);
            #pragma unroll
            for (int i = 0; i < 4; i++) {
                float a = xa[i][kk];
                acc[i][0] = fmaf(a, b.x, acc[i][0]);
                acc[i][1] = fmaf(a, b.y, acc[i][1]);
                acc[i][2] = fmaf(a, b.z, acc[i][2]);
                acc[i][3] = fmaf(a, b.w, acc[i][3]);
            }
        }
    }

    float4 dw = make_float4(0.f, 0.f, 0.f, 0.f);
    if (DOT_OUT) dw = __ldg(reinterpret_cast<const float4*>(dotw) + cg);

    float ssl[4] = {0.f, 0.f, 0.f, 0.f};
    #pragma unroll
    for (int i = 0; i < 4; i++) {
        int r = rowBase + r4 + i;
        float4 a = make_float4(acc[i][0], acc[i][1], acc[i][2], acc[i][3]);
        if (ADDMODE == 1) {
            float4 bb = __ldg(reinterpret_cast<const float4*>(addp) + cg);
            a.x += bb.x; a.y += bb.y; a.z += bb.z; a.w += bb.w;
        } else if (ADDMODE == 2) {
            int ar = ((r >> 1) / NE) * 2 + (r & 1);
            float4 bb = __ldg(reinterpret_cast<const float4*>(addp + (size_t)ar * N) + cg);
            a.x += bb.x; a.y += bb.y; a.z += bb.z; a.w += bb.w;
        } else if (ADDMODE == 3) {
            int ar = r / NE;
            float4 bb = __ldg(reinterpret_cast<const float4*>(addp + (size_t)ar * N) + cg);
            a.x += bb.x; a.y += bb.y; a.z += bb.z; a.w += bb.w;
        }
        if (WITH_SS) {
            ssl[0] += a.x * a.x; ssl[1] += a.y * a.y;
            ssl[2] += a.z * a.z; ssl[3] += a.w * a.w;
        }
        if (RELU) {
            a.x = fmaxf(a.x, 0.f); a.y = fmaxf(a.y, 0.f);
            a.z = fmaxf(a.z, 0.f); a.w = fmaxf(a.w, 0.f);
        }
        if (DOT_OUT) {
            red[(r4 + i) * CG + cg] = a.x * dw.x + a.y * dw.y + a.z * dw.z + a.w * dw.w;
        } else {
            *(reinterpret_cast<float4*>(out + (size_t)r * N) + cg) = a;
        }
    }

    if (DOT_OUT) {
        __syncthreads();
        if (tid < TILE_R) {
            float s = 0.f;
            #pragma unroll
            for (int g = 0; g < CG; g++) s += red[tid * CG + g];
            dotOut[rowBase + tid] = s;
        }
    }
    if (WITH_SS) {
        *reinterpret_cast<float4*>(&red[rg * N + cg * 4]) =
            make_float4(ssl[0], ssl[1], ssl[2], ssl[3]);
        __syncthreads();
        if (tid < N) {
            float s = 0.f;
            #pragma unroll
            for (int g = 0; g < RG; g++) s += red[g * N + tid];
            atomicAdd(ssOut + tid, (double)s);
        }
    }
}

// ---------------- paired-weight GEMM (IE1+IA1 in one pass) ----------------
__global__ void __launch_bounds__(256) gemmpair_k(
    const float* __restrict__ in,               // raw Y2-E
    const float* __restrict__ WE_, const float* __restrict__ WA_,
    const float* __restrict__ addE, const float* __restrict__ addA,
    float* __restrict__ outE, float* __restrict__ outA,
    double* __restrict__ ssE, double* __restrict__ ssA,
    const double* __restrict__ ssIn, double invN)
{
    constexpr int TILE_R = 32;
    __shared__ float xs[TILE_R][68];
    __shared__ float red[8 * 128];
    __shared__ float scs[64];

    const int tid = threadIdx.x;
    const int cg = tid % 32;
    const int rg = tid / 32;
    const int half = cg >> 4;
    const int ch = cg & 15;
    const int rowBase = blockIdx.x * TILE_R;

    if (tid < 64) {
        float m = (float)(ssIn[tid] * invN);
        scs[tid] = __fsqrt_rn(__fadd_rn(m, EPS_));
    }
    __syncthreads();

    {
        int i = tid;
        int pr = i >> 4, c = i & 15;
        const float* p0 = in + (size_t)(rowBase + 2 * pr) * 64 + c * 4;
        float4 v0 = __ldg((const float4*)p0);
        float4 v1 = __ldg((const float4*)(p0 + 64));
        actpair(v0.x, v1.x, scs[c * 4 + 0]);
        actpair(v0.y, v1.y, scs[c * 4 + 1]);
        actpair(v0.z, v1.z, scs[c * 4 + 2]);
        actpair(v0.w, v1.w, scs[c * 4 + 3]);
        *reinterpret_cast<float4*>(&xs[2 * pr][c * 4])     = v0;
        *reinterpret_cast<float4*>(&xs[2 * pr + 1][c * 4]) = v1;
    }
    __syncthreads();

    float acc[4][4];
    #pragma unroll
    for (int i = 0; i < 4; i++)
        #pragma unroll
        for (int j = 0; j < 4; j++) acc[i][j] = 0.f;

    const float4* Wv = reinterpret_cast<const float4*>(half ? WA_ : WE_);
    const int r4 = rg * 4;
    #pragma unroll 2
    for (int k0 = 0; k0 < 64; k0 += 4) {
        float xa[4][4];
        #pragma unroll
        for (int i = 0; i < 4; i++)
            *reinterpret_cast<float4*>(xa[i]) = *reinterpret_cast<const float4*>(&xs[r4 + i][k0]);
        #pragma unroll
        for (int kk = 0; kk < 4; kk++) {
            float4 b = __ldg(Wv + (k0 + kk) * 16 + ch);
            #pragma unroll
            for (int i = 0; i < 4; i++) {
                float a = xa[i][kk];
                acc[i][0] = fmaf(a, b.x, acc[i][0]);
                acc[i][1] = fmaf(a, b.y, acc[i][1]);
                acc[i][2] = fmaf(a, b.z, acc[i][2]);
                acc[i][3] = fmaf(a, b.w, acc[i][3]);
            }
        }
    }

    const float* addp = half ? addA : addE;
    float* out = half ? outA : outE;
    float ssl[4] = {0.f, 0.f, 0.f, 0.f};
    #pragma unroll
    for (int i = 0; i < 4; i++) {
        int r = rowBase + r4 + i;
        float4 a = make_float4(acc[i][0], acc[i][1], acc[i][2], acc[i][3]);
        int ar = ((r >> 1) / NE) * 2 + (r & 1);
        float4 bb = __ldg(reinterpret_cast<const float4*>(addp + (size_t)ar * 64) + ch);
        a.x += bb.x; a.y += bb.y; a.z += bb.z; a.w += bb.w;
        ssl[0] += a.x * a.x; ssl[1] += a.y * a.y;
        ssl[2] += a.z * a.z; ssl[3] += a.w * a.w;
        *(reinterpret_cast<float4*>(out + (size_t)r * 64) + ch) = a;
    }

    *reinterpret_cast<float4*>(&red[rg * 128 + cg * 4]) =
        make_float4(ssl[0], ssl[1], ssl[2], ssl[3]);
    __syncthreads();
    if (tid < 128) {
        float s = 0.f;
        #pragma unroll
        for (int g = 0; g < 8; g++) s += red[g * 128 + tid];
        atomicAdd((tid < 64 ? ssE + tid : ssA + tid - 64), (double)s);
    }
}

// ---------------- fused qmaxpool, 4 channels/thread (float4) ---------------
// Per-channel compare chain identical to scalar version -> bit-identical.
__global__ void __launch_bounds__(256) maxpoolf4_k(
    const float* __restrict__ y2E, const float* __restrict__ y2A,
    const double* __restrict__ ssd, float* __restrict__ pool)
{
    __shared__ float dE[64], dA[64];
    if (threadIdx.x < 64) {
        float mE = (float)(ssd[SS_E2 + threadIdx.x] * (1.0 / REc));
        dE[threadIdx.x] = __fsqrt_rn(__fadd_rn(mE, EPS_));
        float mA = (float)(ssd[SS_A2 + threadIdx.x] * (1.0 / RAc));
        dA[threadIdx.x] = __fsqrt_rn(__fadd_rn(mA, EPS_));
    }
    __syncthreads();
    int idx = blockIdx.x * 256 + threadIdx.x;       // over NAg*16
    if (idx >= NAg * 16) return;
    int agent = idx >> 4, c4 = (idx & 15) * 4;

    float best[4] = {-1.f, -1.f, -1.f, -1.f};
    float b0[4], b1[4];
    #pragma unroll
    for (int j = 0; j < 4; j++) { b0[j] = 0.f; b1[j] = 0.f; }
    float4 de = *reinterpret_cast<const float4*>(&dE[c4]);
    float4 da = *reinterpret_cast<const float4*>(&dA[c4]);
    const float* dep = reinterpret_cast<const float*>(&de);
    const float* dap = reinterpret_cast<const float*>(&da);

    #pragma unroll
    for (int e = 0; e < NE; e++) {
        const float* p = y2E + ((size_t)(agent * NE + e)) * 128 + c4;
        float4 v0 = __ldg((const float4*)p);
        float4 v1 = __ldg((const float4*)(p + 64));
        const float* v0p = reinterpret_cast<const float*>(&v0);
        const float* v1p = reinterpret_cast<const float*>(&v1);
        #pragma unroll
        for (int j = 0; j < 4; j++) {
            float a = v0p[j], b = v1p[j];
            actpair(a, b, dep[j]);
            float m = __fadd_rn(__fmul_rn(a, a), __fmul_rn(b, b));
            if (m > best[j]) { best[j] = m; b0[j] = a; b1[j] = b; }
        }
    }
    #pragma unroll
    for (int e = 0; e < NAL; e++) {
        const float* p = y2A + ((size_t)(agent * NAL + e)) * 128 + c4;
        float4 v0 = __ldg((const float4*)p);
        float4 v1 = __ldg((const float4*)(p + 64));
        const float* v0p = reinterpret_cast<const float*>(&v0);
        const float* v1p = reinterpret_cast<const float*>(&v1);
        #pragma unroll
        for (int j = 0; j < 4; j++) {
            float a = v0p[j], b = v1p[j];
            actpair(a, b, dap[j]);
            float m = __fadd_rn(__fmul_rn(a, a), __fmul_rn(b, b));
            if (m > best[j]) { best[j] = m; b0[j] = a; b1[j] = b; }
        }
    }
    *reinterpret_cast<float4*>(pool + (size_t)agent * 128 + c4) =
        make_float4(b0[0], b0[1], b0[2], b0[3]);
    *reinterpret_cast<float4*>(pool + (size_t)agent * 128 + 64 + c4) =
        make_float4(b1[0], b1[1], b1[2], b1[3]);
}

// ---------------- imp3: fused act + 64->1 dot per pair + scalar sumsq ------
__global__ void __launch_bounds__(256) imp3f_k(
    const float* __restrict__ yi2,
    const float* __restrict__ wE, const float* __restrict__ wA,
    float* __restrict__ y3, double* __restrict__ ssd)
{
    constexpr int EBLK = PEc / 256;  // 400
    const int reg = (blockIdx.x >= EBLK) ? 1 : 0;
    const int pl = (blockIdx.x - reg * EBLK) * 256 + threadIdx.x;

    __shared__ float rcs[64];
    if (threadIdx.x < 64) {
        float m = (float)(ssd[(reg ? SS_IA2 : SS_IE2) + threadIdx.x] * (1.0 / REc));
        rcs[threadIdx.x] = __fsqrt_rn(__fadd_rn(m, EPS_));
    }
    __syncthreads();

    int gp = reg ? (PEc + pl) : pl;
    const float* src = yi2 + (size_t)(2 * gp) * 64;
    const float* w = reg ? wA : wE;

    float s0 = 0.f, s1 = 0.f;
    #pragma unroll
    for (int k4 = 0; k4 < 16; k4++) {
        float4 v0 = __ldg(reinterpret_cast<const float4*>(src) + k4);
        float4 v1 = __ldg(reinterpret_cast<const float4*>(src + 64) + k4);
        float4 dn = *reinterpret_cast<const float4*>(&rcs[k4 * 4]);
        float4 wv = __ldg(reinterpret_cast<const float4*>(w) + k4);
        #pragma unroll
        for (int j = 0; j < 4; j++) {
            float a = ((const float*)&v0)[j];
            float b = ((const float*)&v1)[j];
            actpair(a, b, ((const float*)&dn)[j]);
            float ww = ((const float*)&wv)[j];
            s0 = fmaf(a, ww, s0);
            s1 = fmaf(b, ww, s1);
        }
    }
    y3[2 * gp] = s0;
    y3[2 * gp + 1] = s1;

    __shared__ float red[256];
    red[threadIdx.x] = s0 * s0 + s1 * s1;
    __syncthreads();
    for (int o = 128; o > 0; o >>= 1) {
        if (threadIdx.x < o) red[threadIdx.x] += red[threadIdx.x + o];
        __syncthreads();
    }
    if (threadIdx.x == 0) atomicAdd(ssd + (reg ? SS_IA3 : SS_IE3), (double)red[0]);
}

// ---------------- move_vec accumulation ----------------
__global__ void mv_k(const float* __restrict__ y3, const double* __restrict__ ssd,
                     float* __restrict__ mv)
{
    int idx = blockIdx.x * blockDim.x + threadIdx.x;
    if (idx >= 2 * PEc) return;
    bool isE = idx < PEc;
    int p = isE ? idx : idx - PEc;
    float m = (float)(ssd[isE ? SS_IE3 : SS_IA3] * (1.0 / REc));
    float denom = __fsqrt_rn(__fadd_rn(m, EPS_));
    size_t base = (isE ? (size_t)0 : (size_t)REc) + (size_t)p * 2;
    float b0 = __fdiv_rn(y3[base], denom);
    float b1 = __fdiv_rn(y3[base + 1], denom);
    float mod = __fsqrt_rn(__fadd_rn(__fmul_rn(b0, b0), __fmul_rn(b1, b1)));
    float coeff = fminf(mod, 1.f);
    int agent = p / NE;
    atomicAdd(mv + agent * 2,     __fmul_rn(b0, coeff));
    atomicAdd(mv + agent * 2 + 1, __fmul_rn(b1, coeff));
}

// ---------------- final assembly ----------------
__device__ __forceinline__ float wred(float v) {
    #pragma unroll
    for (int o = 16; o; o >>= 1) v += __shfl_xor_sync(0xffffffffu, v, o);
    return v;
}

__global__ void __launch_bounds__(256) final_k(
    const float* __restrict__ oah, const float* __restrict__ Woa2,
    const float* __restrict__ boa2,
    const float* __restrict__ aqbuf, const float* __restrict__ bat3,
    const float* __restrict__ mv, float* __restrict__ out)
{
    int agent = blockIdx.x * 8 + (threadIdx.x >> 5);
    int lane = threadIdx.x & 31;
    const float* oa = oah + (size_t)agent * 64;
    float o0 = oa[2 * lane], o1 = oa[2 * lane + 1];
    float q[3];
    #pragma unroll
    for (int j = 0; j < 3; j++) {
        float part = o0 * __ldg(Woa2 + (2 * lane) * 3 + j)
                   + o1 * __ldg(Woa2 + (2 * lane + 1) * 3 + j);
        q[j] = wred(part);
    }
    float* o = out + (size_t)agent * 16;
    if (lane == 0) {
        float q2 = q[2] + boa2[2];
        float m0 = mv[agent * 2], m1 = mv[agent * 2 + 1];
        o[0] = q[0] + boa2[0];
        o[1] = q[1] + boa2[1];
        o[2] = q2 + m1;
        o[3] = q2 - m1;
        o[4] = q2 + m0;
        o[5] = q2 - m0;
    }
    if (lane < NE)
        o[6 + lane] = aqbuf[(size_t)agent * NE + lane] + bat3[0];
}

// ---------------- launcher ----------------
extern "C" void kernel_launch(void* const* d_in, const int* in_sizes, int n_in,
                              void* d_out, int out_size)
{
    const float* own   = (const float*)d_in[0];
    const float* ef    = (const float*)d_in[1];
    const float* af    = (const float*)d_in[2];
    const float* W_e1  = (const float*)d_in[3];
    const float* W_e2  = (const float*)d_in[4];
    const float* W_a1  = (const float*)d_in[5];
    const float* W_a2  = (const float*)d_in[6];
    const float* W_f1  = (const float*)d_in[7];
    const float* W_f2  = (const float*)d_in[8];
    const float* W_ie1 = (const float*)d_in[9];
    const float* W_ie2 = (const float*)d_in[10];
    const float* W_ie3 = (const float*)d_in[11];
    const float* W_ia1 = (const float*)d_in[12];
    const float* W_ia2 = (const float*)d_in[13];
    const float* W_ia3 = (const float*)d_in[14];
    const float* W_oa1 = (const float*)d_in[15];
    const float* b_oa1 = (const float*)d_in[16];
    const float* W_oa2 = (const float*)d_in[17];
    const float* b_oa2 = (const float*)d_in[18];
    const float* W_at1 = (const float*)d_in[19];
    const float* b_at1 = (const float*)d_in[20];
    const float* W_at2 = (const float*)d_in[21];
    const float* b_at2 = (const float*)d_in[22];
    const float* W_at3 = (const float*)d_in[23];
    const float* b_at3 = (const float*)d_in[24];
    float* out = (float*)d_out;

    float* S = nullptr;
    cudaGetSymbolAddress((void**)&S, g_scratch);
    double* ssd = nullptr;
    cudaGetSymbolAddress((void**)&ssd, g_ssd);

    zero_k<<<80, 256>>>(S + OFF_MV, ssd);

    // layer 1 (ref-exact build_vec + W_e1/W_a1), raw output + ss E1/A1
    layer1_k<<<(PEc + PAc) / 32, 64>>>(own, ef, af, W_e1, W_a1, S + OFF_Y1, ssd);

    // layer 2, dual region, act(Y1) fused on load, ss E2/A2 (Y2 stays RAW)
    gemm_k<64, 64, 0, false, true, 1, false><<<RTc / 64, 256>>>(
        REc / 64,
        S + OFF_Y1, S + OFF_Y1 + (size_t)REc * 64,
        S + OFF_Y2, S + OFF_Y2 + (size_t)REc * 64,
        W_e2, W_a2, nullptr, nullptr,
        ssd + SS_E2, ssd + SS_A2,
        ssd + SS_E1, ssd + SS_A1, 1.0 / REc, 1.0 / RAc,
        nullptr, nullptr);

    // fused act + qmaxpool on raw Y2 (4 channels/thread)
    maxpoolf4_k<<<(NAg * 16) / 256, 256>>>(S + OFF_Y2, S + OFF_Y2 + (size_t)REc * 64,
                                           ssd, S + OFF_POOL);
    gemm_k<64, 64, 0, false, true, 0, false><<<(2 * NAg) / 64, 256>>>(
        (2 * NAg) / 64, S + OFF_POOL, S + OFF_POOL, S + OFF_YF1, S + OFF_YF1,
        W_f1, W_f1, nullptr, nullptr, ssd + SS_F1, ssd + SS_F1,
        nullptr, nullptr, 0.0, 0.0, nullptr, nullptr);
    gemm_k<64, 64, 0, false, true, 1, false><<<(2 * NAg) / 64, 256>>>(
        (2 * NAg) / 64, S + OFF_YF1, S + OFF_YF1, S + OFF_VF, S + OFF_VF,
        W_f2, W_f2, nullptr, nullptr, ssd + SS_F2, ssd + SS_F2,
        ssd + SS_F1, ssd + SS_F1, 1.0 / (2 * NAg), 1.0 / (2 * NAg), nullptr, nullptr);
    act_k<<<(NAg * 64) / 256, 256>>>(S + OFF_VF, ssd + SS_F2, NAg, 1.0 / (2 * NAg), S + OFF_SF);

    // vf @ top-half of W_ie1 / W_ia1 (dual; VF act'd in place)
    gemm_k<64, 64, 0, false, false, 0, false><<<2 * ((2 * NAg) / 64), 256>>>(
        (2 * NAg) / 64, S + OFF_VF, S + OFF_VF, S + OFF_VCE, S + OFF_VCA,
        W_ie1, W_ia1, nullptr, nullptr, nullptr, nullptr,
        nullptr, nullptr, 0.0, 0.0, nullptr, nullptr);

    // importance layer 1: PAIRED kernel (one pass over raw Y2-E, act on load)
    gemmpair_k<<<REc / 32, 256>>>(
        S + OFF_Y2, W_ie1 + 64 * 64, W_ia1 + 64 * 64,
        S + OFF_VCE, S + OFF_VCA,
        S + OFF_YI1E, S + OFF_YI1A,
        ssd + SS_IE1, ssd + SS_IA1,
        ssd + SS_E2, 1.0 / REc);

    // importance layer 2 (dual, act fused on load), ss IE2/IA2
    gemm_k<64, 64, 0, false, true, 1, false><<<2 * (REc / 64), 256>>>(
        REc / 64, S + OFF_YI1E, S + OFF_YI1A, S + OFF_YI2E, S + OFF_YI2A,
        W_ie2, W_ia2, nullptr, nullptr,
        ssd + SS_IE2, ssd + SS_IA2,
        ssd + SS_IE1, ssd + SS_IA1, 1.0 / REc, 1.0 / REc, nullptr, nullptr);

    // importance layer 3 (act fused) + move vec — BOTH regions PEc pairs
    imp3f_k<<<2 * (PEc / 256), 256>>>(S + OFF_YI2E, W_ie3, W_ia3, S + OFF_Y3, ssd);
    mv_k<<<(2 * PEc + 255) / 256, 256>>>(S + OFF_Y3, ssd, S + OFF_MV);

    // oaq hidden
    gemm_k<64, 64, 1, true, false, 0, false><<<NAg / 64, 256>>>(
        NAg / 64, S + OFF_SF, S + OFF_SF, S + OFF_OAH, S + OFF_OAH,
        W_oa1, W_oa1, b_oa1, b_oa1, nullptr, nullptr,
        nullptr, nullptr, 0.0, 0.0, nullptr, nullptr);

    // attention head: sf@W_at1_top + bias (per agent)
    gemm_k<64, 128, 1, false, false, 0, false><<<NAg / 32, 256>>>(
        NAg / 32, S + OFF_SF, S + OFF_SF, S + OFF_SFC, S + OFF_SFC,
        W_at1, W_at1, b_at1, b_at1, nullptr, nullptr,
        nullptr, nullptr, 0.0, 0.0, nullptr, nullptr);
    // H1 = relu(e_scalar@W_at1_bot + SFC[agent]) — e_scalar computed on load
    gemm_k<64, 128, 3, true, false, 2, false><<<PEc / 32, 256>>>(
        PEc / 32, S + OFF_Y2, S + OFF_Y2, S + OFF_H1, S + OFF_H1,
        W_at1 + 64 * 128, W_at1 + 64 * 128, S + OFF_SFC, S + OFF_SFC,
        nullptr, nullptr, ssd + SS_E2, ssd + SS_E2, 1.0 / REc, 1.0 / REc,
        nullptr, nullptr);
    // H2 with fused W_at3 dot -> aq
    gemm_k<128, 64, 1, true, false, 0, true><<<PEc / 64, 256>>>(
        PEc / 64, S + OFF_H1, S + OFF_H1, nullptr, nullptr,
        W_at2, W_at2, b_at2, b_at2, nullptr, nullptr,
        nullptr, nullptr, 0.0, 0.0, W_at3, S + OFF_AQ);

    final_k<<<NAg / 8, 256>>>(S + OFF_OAH, W_oa2, b_oa2, S + OFF_AQ, b_at3, S + OFF_MV, out);

    (void)in_sizes; (void)n_in; (void)out_size;
}

// round 14
// speedup vs baseline: 1.1730x; 1.0876x over previous
#include <cuda_runtime.h>

// ---------------- problem constants ----------------
constexpr int NAg = 10240;           // B*NA agents
constexpr int NE  = 10, NAL = 9;
constexpr int PEc = NAg * NE;        // 102400 enemy pairs
constexpr int PAc = NAg * NAL;       // 92160 ally pairs
constexpr int REc = 2 * PEc;         // 204800 enemy rows
constexpr int RAc = 2 * PAc;         // 184320 ally rows
constexpr int RTc = REc + RAc;       // 389120
constexpr float EPS_ = 1e-5f;

// sumsq slots (within double ss block)
constexpr int SS_E1 = 0,   SS_A1 = 64,  SS_E2 = 128, SS_A2 = 192;
constexpr int SS_F1 = 256, SS_F2 = 320;
constexpr int SS_IE1 = 384, SS_IA1 = 448, SS_IE2 = 512, SS_IA2 = 576;
constexpr int SS_IE3 = 640, SS_IA3 = 641;

// ---------------- scratch layout (floats) ----------------
constexpr size_t OFF_Y1   = 0;
constexpr size_t OFF_Y2   = OFF_Y1   + (size_t)RTc * 64;
constexpr size_t OFF_POOL = OFF_Y2   + (size_t)RTc * 64;
constexpr size_t OFF_YF1  = OFF_POOL + (size_t)NAg * 128;
constexpr size_t OFF_VF   = OFF_YF1  + (size_t)NAg * 128;
constexpr size_t OFF_SF   = OFF_VF   + (size_t)NAg * 128;
constexpr size_t OFF_VCE  = OFF_SF   + (size_t)NAg * 64;
constexpr size_t OFF_VCA  = OFF_VCE  + (size_t)NAg * 128;
constexpr size_t OFF_SFC  = OFF_VCA  + (size_t)NAg * 128;
constexpr size_t OFF_YI1E = OFF_SFC  + (size_t)NAg * 128;
constexpr size_t OFF_YI1A = OFF_YI1E + (size_t)REc * 64;
constexpr size_t OFF_YI2E = OFF_YI1A + (size_t)REc * 64;
constexpr size_t OFF_YI2A = OFF_YI2E + (size_t)REc * 64;
constexpr size_t OFF_Y3   = OFF_YI2A + (size_t)REc * 64;
constexpr size_t OFF_AQ   = OFF_Y3   + (size_t)2 * REc;
constexpr size_t OFF_OAH  = OFF_AQ   + (size_t)PEc;
constexpr size_t OFF_MV   = OFF_OAH  + (size_t)NAg * 64;
constexpr size_t SCR_TOTAL = OFF_MV + 20480;

__device__ __align__(16) float g_scratch[SCR_TOTAL];
__device__ __align__(16) double g_ssd[768];

// ---------------- zero kernel (mv floats + ss doubles) ----------------
__global__ void zero_k(float* __restrict__ mv, double* __restrict__ ssd) {
    int i = blockIdx.x * 256 + threadIdx.x;
    if (i < 20480) mv[i] = 0.f;
    if (i < 768) ssd[i] = 0.0;
}

// ---------------- ref-exact qbn+qrelu pair op ----------------
__device__ __forceinline__ void actpair(float& a, float& b, float denom) {
    a = __fdiv_rn(a, denom);
    b = __fdiv_rn(b, denom);
    float mod = __fsqrt_rn(__fadd_rn(__fmul_rn(a, a), __fmul_rn(b, b)));
    float coeff = fminf(mod, 1.f);          // == mod/max(1,mod) exactly
    a = __fmul_rn(a, coeff);
    b = __fmul_rn(b, coeff);
}

// ---------------- layer1: build_vec (ref-exact fp32) + 19-dot + sumsq ------
__global__ void __launch_bounds__(64) layer1_k(
    const float* __restrict__ own, const float* __restrict__ efeat,
    const float* __restrict__ afeat, const float* __restrict__ We,
    const float* __restrict__ Wa, float* __restrict__ y1,
    double* __restrict__ ssd)
{
    constexpr int PPB = 32;
    constexpr int EBLK = PEc / PPB;  // 3200
    const bool isE = blockIdx.x < EBLK;
    const int pbase = (isE ? blockIdx.x : blockIdx.x - EBLK) * PPB;
    const float* W = isE ? We : Wa;
    const float* feats = isE ? efeat : afeat;
    const int nper = isE ? NE : NAL;
    const int tid = threadIdx.x;

    __shared__ float ev0[PPB][20];
    __shared__ float ev1[PPB][20];

    if (tid < PPB) {
        int p = pbase + tid;
        const float* f = feats + (size_t)p * 9;
        const float* o = own + (size_t)(p / nper) * 11;
        float f2 = f[2], f3 = f[3];
        float pm = __fsqrt_rn(__fadd_rn(__fmul_rn(f2, f2), __fmul_rn(f3, f3)));
        bool mask = (pm == 0.f);
        float denom = mask ? 1.f : pm;
        ev0[tid][0] = f2; ev1[tid][0] = f3;
        float oth[7] = { f[0], f[1], f[4], f[5], f[6], f[7], f[8] };
        #pragma unroll
        for (int k = 0; k < 7; k++) {
            float om = __fsqrt_rn(__fmul_rn(2.f * oth[k], oth[k]));
            float u = mask ? 0.f : __fdiv_rn(om, denom);
            ev0[tid][1 + k] = __fmul_rn(f2, u);
            ev1[tid][1 + k] = __fmul_rn(f3, u);
        }
        #pragma unroll
        for (int k = 0; k < 11; k++) {
            float q = __fmul_rn(o[k], o[k]);
            float om = __fsqrt_rn(__fadd_rn(q, q));
            float u = mask ? 0.f : __fdiv_rn(om, denom);
            ev0[tid][8 + k] = __fmul_rn(f2, u);
            ev1[tid][8 + k] = __fmul_rn(f3, u);
        }
    }
    __syncthreads();

    float wr[19];
    #pragma unroll
    for (int k = 0; k < 19; k++) wr[k] = __ldg(W + k * 64 + tid);

    float ssa = 0.f;
    size_t rowG0 = (isE ? (size_t)0 : (size_t)REc) + (size_t)pbase * 2;
    for (int j = 0; j < PPB; j++) {
        float s0 = 0.f, s1 = 0.f;
        #pragma unroll
        for (int k = 0; k < 19; k++) {
            s0 = fmaf(ev0[j][k], wr[k], s0);
            s1 = fmaf(ev1[j][k], wr[k], s1);
        }
        y1[(rowG0 + 2 * j) * 64 + tid]     = s0;
        y1[(rowG0 + 2 * j + 1) * 64 + tid] = s1;
        ssa += s0 * s0 + s1 * s1;
    }
    atomicAdd(ssd + (isE ? SS_E1 : SS_A1) + tid, (double)ssa);
}

// ---------------- standalone act (VF only): in-place + merge ----------------
__global__ void act_k(float* __restrict__ y, const double* __restrict__ ssd,
                      int npairs, double invN, float* __restrict__ mergeOut)
{
    __shared__ float dsh[64];
    if (threadIdx.x < 64) {
        float m = (float)(ssd[threadIdx.x] * invN);
        dsh[threadIdx.x] = __fsqrt_rn(__fadd_rn(m, EPS_));
    }
    __syncthreads();
    int idx = blockIdx.x * 256 + threadIdx.x;
    if (idx >= npairs * 64) return;
    int p = idx >> 6, c = idx & 63;
    size_t i0 = (size_t)p * 128 + c;
    float a = y[i0], b = y[i0 + 64];
    actpair(a, b, dsh[c]);
    y[i0] = a; y[i0 + 64] = b;
    if (mergeOut)
        mergeOut[(size_t)p * 64 + c] = __fadd_rn(__fmul_rn(a, a), __fmul_rn(b, b));
}

// ---------------- generic dual-region GEMM (scalar FFMA core) ----------------
// ADDMODE: 0 none; 1 bias (N); 2 ar=((r>>1)/NE)*2+(r&1); 3 ar=r/NE  (r local)
// INMODE: 0 plain; 1 act-on-load (pairs, K=64)
template<int K, int N, int ADDMODE, bool RELU, bool WITH_SS, int INMODE>
__global__ void __launch_bounds__(256) gemm_k(
    int splitBlk,
    const float* __restrict__ inA, const float* __restrict__ inB,
    float* __restrict__ outA, float* __restrict__ outB,
    const float* __restrict__ WA_, const float* __restrict__ WB_,
    const float* __restrict__ addA, const float* __restrict__ addB,
    double* __restrict__ ssOutA, double* __restrict__ ssOutB,
    const double* __restrict__ ssInA, const double* __restrict__ ssInB,
    double invNA, double invNB)
{
    const int reg = (blockIdx.x >= splitBlk) ? 1 : 0;
    const int blk = blockIdx.x - reg * splitBlk;
    const float* in  = reg ? inB  : inA;
    float* out       = reg ? outB : outA;
    const float* W   = reg ? WB_  : WA_;
    const float* addp= reg ? addB : addA;
    double* ssOut    = reg ? ssOutB : ssOutA;

    constexpr int CG = N / 4;
    constexpr int RG = 256 / CG;
    constexpr int TILE_R = RG * 4;
    __shared__ float xs[TILE_R][K + 4];
    __shared__ float red[WITH_SS ? RG * N : 1];
    __shared__ float scs[(INMODE != 0) ? 64 : 1];

    const int tid = threadIdx.x;
    const int cg = tid % CG;
    const int rg = tid / CG;
    const int rowBase = blk * TILE_R;

    if (INMODE != 0) {
        const double* ssIn = reg ? ssInB : ssInA;
        double invN = reg ? invNB : invNA;
        if (tid < 64) {
            float m = (float)(ssIn[tid] * invN);
            scs[tid] = __fsqrt_rn(__fadd_rn(m, EPS_));
        }
        __syncthreads();
    }

    if (INMODE == 1) {
        #pragma unroll
        for (int i = tid; i < (TILE_R / 2) * 16; i += 256) {
            int pr = i >> 4, c = i & 15;
            const float* p0 = in + (size_t)(rowBase + 2 * pr) * 64 + c * 4;
            float4 v0 = __ldg((const float4*)p0);
            float4 v1 = __ldg((const float4*)(p0 + 64));
            actpair(v0.x, v1.x, scs[c * 4 + 0]);
            actpair(v0.y, v1.y, scs[c * 4 + 1]);
            actpair(v0.z, v1.z, scs[c * 4 + 2]);
            actpair(v0.w, v1.w, scs[c * 4 + 3]);
            *reinterpret_cast<float4*>(&xs[2 * pr][c * 4])     = v0;
            *reinterpret_cast<float4*>(&xs[2 * pr + 1][c * 4]) = v1;
        }
    } else {
        constexpr int KV = K / 4;
        #pragma unroll
        for (int i = tid; i < TILE_R * KV; i += 256) {
            int r = i / KV, c = i - r * KV;
            float4 v = __ldg(reinterpret_cast<const float4*>(in + (size_t)(rowBase + r) * K) + c);
            *reinterpret_cast<float4*>(&xs[r][c * 4]) = v;
        }
    }
    __syncthreads();

    float acc[4][4];
    #pragma unroll
    for (int i = 0; i < 4; i++)
        #pragma unroll
        for (int j = 0; j < 4; j++) acc[i][j] = 0.f;

    const float4* Wv = reinterpret_cast<const float4*>(W);
    const int r4 = rg * 4;
    #pragma unroll 2
    for (int k0 = 0; k0 < K; k0 += 4) {
        float xa[4][4];
        #pragma unroll
        for (int i = 0; i < 4; i++)
            *reinterpret_cast<float4*>(xa[i]) = *reinterpret_cast<const float4*>(&xs[r4 + i][k0]);
        #pragma unroll
        for (int kk = 0; kk < 4; kk++) {
            float4 b = __ldg(Wv + (k0 + kk) * CG + cg);
            #pragma unroll
            for (int i = 0; i < 4; i++) {
                float a = xa[i][kk];
                acc[i][0] = fmaf(a, b.x, acc[i][0]);
                acc[i][1] = fmaf(a, b.y, acc[i][1]);
                acc[i][2] = fmaf(a, b.z, acc[i][2]);
                acc[i][3] = fmaf(a, b.w, acc[i][3]);
            }
        }
    }

    float ssl[4] = {0.f, 0.f, 0.f, 0.f};
    #pragma unroll
    for (int i = 0; i < 4; i++) {
        int r = rowBase + r4 + i;
        float4 a = make_float4(acc[i][0], acc[i][1], acc[i][2], acc[i][3]);
        if (ADDMODE == 1) {
            float4 bb = __ldg(reinterpret_cast<const float4*>(addp) + cg);
            a.x += bb.x; a.y += bb.y; a.z += bb.z; a.w += bb.w;
        } else if (ADDMODE == 2) {
            int ar = ((r >> 1) / NE) * 2 + (r & 1);
            float4 bb = __ldg(reinterpret_cast<const float4*>(addp + (size_t)ar * N) + cg);
            a.x += bb.x; a.y += bb.y; a.z += bb.z; a.w += bb.w;
        } else if (ADDMODE == 3) {
            int ar = r / NE;
            float4 bb = __ldg(reinterpret_cast<const float4*>(addp + (size_t)ar * N) + cg);
            a.x += bb.x; a.y += bb.y; a.z += bb.z; a.w += bb.w;
        }
        if (WITH_SS) {
            ssl[0] += a.x * a.x; ssl[1] += a.y * a.y;
            ssl[2] += a.z * a.z; ssl[3] += a.w * a.w;
        }
        if (RELU) {
            a.x = fmaxf(a.x, 0.f); a.y = fmaxf(a.y, 0.f);
            a.z = fmaxf(a.z, 0.f); a.w = fmaxf(a.w, 0.f);
        }
        *(reinterpret_cast<float4*>(out + (size_t)r * N) + cg) = a;
    }

    if (WITH_SS) {
        *reinterpret_cast<float4*>(&red[rg * N + cg * 4]) =
            make_float4(ssl[0], ssl[1], ssl[2], ssl[3]);
        __syncthreads();
        if (tid < N) {
            float s = 0.f;
            #pragma unroll
            for (int g = 0; g < RG; g++) s += red[g * N + tid];
            atomicAdd(ssOut + tid, (double)s);
        }
    }
}

// ---------------- paired-weight GEMM (IE1+IA1 in one pass) ----------------
__global__ void __launch_bounds__(256) gemmpair_k(
    const float* __restrict__ in,               // raw Y2-E
    const float* __restrict__ WE_, const float* __restrict__ WA_,
    const float* __restrict__ addE, const float* __restrict__ addA,
    float* __restrict__ outE, float* __restrict__ outA,
    double* __restrict__ ssE, double* __restrict__ ssA,
    const double* __restrict__ ssIn, double invN)
{
    constexpr int TILE_R = 32;
    __shared__ float xs[TILE_R][68];
    __shared__ float red[8 * 128];
    __shared__ float scs[64];

    const int tid = threadIdx.x;
    const int cg = tid % 32;
    const int rg = tid / 32;
    const int half = cg >> 4;
    const int ch = cg & 15;
    const int rowBase = blockIdx.x * TILE_R;

    if (tid < 64) {
        float m = (float)(ssIn[tid] * invN);
        scs[tid] = __fsqrt_rn(__fadd_rn(m, EPS_));
    }
    __syncthreads();

    {
        int i = tid;
        int pr = i >> 4, c = i & 15;
        const float* p0 = in + (size_t)(rowBase + 2 * pr) * 64 + c * 4;
        float4 v0 = __ldg((const float4*)p0);
        float4 v1 = __ldg((const float4*)(p0 + 64));
        actpair(v0.x, v1.x, scs[c * 4 + 0]);
        actpair(v0.y, v1.y, scs[c * 4 + 1]);
        actpair(v0.z, v1.z, scs[c * 4 + 2]);
        actpair(v0.w, v1.w, scs[c * 4 + 3]);
        *reinterpret_cast<float4*>(&xs[2 * pr][c * 4])     = v0;
        *reinterpret_cast<float4*>(&xs[2 * pr + 1][c * 4]) = v1;
    }
    __syncthreads();

    float acc[4][4];
    #pragma unroll
    for (int i = 0; i < 4; i++)
        #pragma unroll
        for (int j = 0; j < 4; j++) acc[i][j] = 0.f;

    const float4* Wv = reinterpret_cast<const float4*>(half ? WA_ : WE_);
    const int r4 = rg * 4;
    #pragma unroll 2
    for (int k0 = 0; k0 < 64; k0 += 4) {
        float xa[4][4];
        #pragma unroll
        for (int i = 0; i < 4; i++)
            *reinterpret_cast<float4*>(xa[i]) = *reinterpret_cast<const float4*>(&xs[r4 + i][k0]);
        #pragma unroll
        for (int kk = 0; kk < 4; kk++) {
            float4 b = __ldg(Wv + (k0 + kk) * 16 + ch);
            #pragma unroll
            for (int i = 0; i < 4; i++) {
                float a = xa[i][kk];
                acc[i][0] = fmaf(a, b.x, acc[i][0]);
                acc[i][1] = fmaf(a, b.y, acc[i][1]);
                acc[i][2] = fmaf(a, b.z, acc[i][2]);
                acc[i][3] = fmaf(a, b.w, acc[i][3]);
            }
        }
    }

    const float* addp = half ? addA : addE;
    float* out = half ? outA : outE;
    float ssl[4] = {0.f, 0.f, 0.f, 0.f};
    #pragma unroll
    for (int i = 0; i < 4; i++) {
        int r = rowBase + r4 + i;
        float4 a = make_float4(acc[i][0], acc[i][1], acc[i][2], acc[i][3]);
        int ar = ((r >> 1) / NE) * 2 + (r & 1);
        float4 bb = __ldg(reinterpret_cast<const float4*>(addp + (size_t)ar * 64) + ch);
        a.x += bb.x; a.y += bb.y; a.z += bb.z; a.w += bb.w;
        ssl[0] += a.x * a.x; ssl[1] += a.y * a.y;
        ssl[2] += a.z * a.z; ssl[3] += a.w * a.w;
        *(reinterpret_cast<float4*>(out + (size_t)r * 64) + ch) = a;
    }

    *reinterpret_cast<float4*>(&red[rg * 128 + cg * 4]) =
        make_float4(ssl[0], ssl[1], ssl[2], ssl[3]);
    __syncthreads();
    if (tid < 128) {
        float s = 0.f;
        #pragma unroll
        for (int g = 0; g < 8; g++) s += red[g * 128 + tid];
        atomicAdd((tid < 64 ? ssE + tid : ssA + tid - 64), (double)s);
    }
}

// ---------------- fused qmaxpool: act applied inline on raw Y2 -------------
__global__ void maxpoolf_k(const float* __restrict__ y2E,
                           const float* __restrict__ y2A,
                           const double* __restrict__ ssd,
                           float* __restrict__ pool)
{
    __shared__ float dE[64], dA[64];
    if (threadIdx.x < 64) {
        float mE = (float)(ssd[SS_E2 + threadIdx.x] * (1.0 / REc));
        dE[threadIdx.x] = __fsqrt_rn(__fadd_rn(mE, EPS_));
        float mA = (float)(ssd[SS_A2 + threadIdx.x] * (1.0 / RAc));
        dA[threadIdx.x] = __fsqrt_rn(__fadd_rn(mA, EPS_));
    }
    __syncthreads();
    int idx = blockIdx.x * 256 + threadIdx.x;
    if (idx >= NAg * 64) return;
    int agent = idx >> 6, c = idx & 63;
    float best = -1.f, b0 = 0.f, b1 = 0.f;
    float de = dE[c], da = dA[c];
    #pragma unroll
    for (int e = 0; e < NE; e++) {
        size_t r = ((size_t)(agent * NE + e)) * 128 + c;
        float v0 = __ldg(y2E + r), v1 = __ldg(y2E + r + 64);
        actpair(v0, v1, de);
        float m = __fadd_rn(__fmul_rn(v0, v0), __fmul_rn(v1, v1));
        if (m > best) { best = m; b0 = v0; b1 = v1; }
    }
    #pragma unroll
    for (int e = 0; e < NAL; e++) {
        size_t r = ((size_t)(agent * NAL + e)) * 128 + c;
        float v0 = __ldg(y2A + r), v1 = __ldg(y2A + r + 64);
        actpair(v0, v1, da);
        float m = __fadd_rn(__fmul_rn(v0, v0), __fmul_rn(v1, v1));
        if (m > best) { best = m; b0 = v0; b1 = v1; }
    }
    pool[(size_t)agent * 128 + c] = b0;
    pool[(size_t)agent * 128 + 64 + c] = b1;
}

// ---------------- fused attention: merge -> GEMM1 -> GEMM2 -> dot ----------
__global__ void __launch_bounds__(256) attn_k(
    const float* __restrict__ y2E,     // raw Y2-E (pairs of rows)
    const float* __restrict__ Wb,      // W_at1 bottom half (64,128)
    const float* __restrict__ sfc,     // (NAg,128) sf@W_at1_top + b_at1
    const float* __restrict__ W2,      // W_at2 (128,64)
    const float* __restrict__ b2,      // (64)
    const float* __restrict__ w3,      // (64) W_at3
    float* __restrict__ aq,            // (PEc)
    const double* __restrict__ ssd)    // ssd + SS_E2
{
    constexpr int TP = 32;
    __shared__ float xs[TP][68];       // merged e_scalar
    __shared__ float hs[TP][132];      // post-at1 hidden
    __shared__ float scs[64];
    __shared__ float red[TP * 16];

    const int tid = threadIdx.x;
    const int pBase = blockIdx.x * TP;

    if (tid < 64) {
        float m = (float)(ssd[tid] * (1.0 / REc));
        scs[tid] = __fsqrt_rn(__fadd_rn(m, EPS_));
    }
    __syncthreads();

    // merge-on-load: xs[pr][c] = act(a)^2 + act(b)^2
    #pragma unroll
    for (int i = tid; i < TP * 16; i += 256) {
        int pr = i >> 4, c = i & 15;
        const float* p0 = y2E + (size_t)(pBase + pr) * 128 + c * 4;
        float4 v0 = __ldg((const float4*)p0);
        float4 v1 = __ldg((const float4*)(p0 + 64));
        actpair(v0.x, v1.x, scs[c * 4 + 0]);
        actpair(v0.y, v1.y, scs[c * 4 + 1]);
        actpair(v0.z, v1.z, scs[c * 4 + 2]);
        actpair(v0.w, v1.w, scs[c * 4 + 3]);
        float4 mg;
        mg.x = __fadd_rn(__fmul_rn(v0.x, v0.x), __fmul_rn(v1.x, v1.x));
        mg.y = __fadd_rn(__fmul_rn(v0.y, v0.y), __fmul_rn(v1.y, v1.y));
        mg.z = __fadd_rn(__fmul_rn(v0.z, v0.z), __fmul_rn(v1.z, v1.z));
        mg.w = __fadd_rn(__fmul_rn(v0.w, v0.w), __fmul_rn(v1.w, v1.w));
        *reinterpret_cast<float4*>(&xs[pr][c * 4]) = mg;
    }
    __syncthreads();

    // GEMM1: K=64 -> N=128, + SFC[agent] add, relu -> hs
    {
        const int cg = tid & 31, rg = tid >> 5;
        const int r4 = rg * 4;
        float acc[4][4];
        #pragma unroll
        for (int i = 0; i < 4; i++)
            #pragma unroll
            for (int j = 0; j < 4; j++) acc[i][j] = 0.f;
        const float4* Wv = reinterpret_cast<const float4*>(Wb);
        #pragma unroll 2
        for (int k0 = 0; k0 < 64; k0 += 4) {
            float xa[4][4];
            #pragma unroll
            for (int i = 0; i < 4; i++)
                *reinterpret_cast<float4*>(xa[i]) = *reinterpret_cast<const float4*>(&xs[r4 + i][k0]);
            #pragma unroll
            for (int kk = 0; kk < 4; kk++) {
                float4 b = __ldg(Wv + (k0 + kk) * 32 + cg);
                #pragma unroll
                for (int i = 0; i < 4; i++) {
                    float a = xa[i][kk];
                    acc[i][0] = fmaf(a, b.x, acc[i][0]);
                    acc[i][1] = fmaf(a, b.y, acc[i][1]);
                    acc[i][2] = fmaf(a, b.z, acc[i][2]);
                    acc[i][3] = fmaf(a, b.w, acc[i][3]);
                }
            }
        }
        #pragma unroll
        for (int i = 0; i < 4; i++) {
            int gp = pBase + r4 + i;
            int ar = gp / NE;
            float4 bb = __ldg(reinterpret_cast<const float4*>(sfc + (size_t)ar * 128) + cg);
            float4 a = make_float4(acc[i][0] + bb.x, acc[i][1] + bb.y,
                                   acc[i][2] + bb.z, acc[i][3] + bb.w);
            a.x = fmaxf(a.x, 0.f); a.y = fmaxf(a.y, 0.f);
            a.z = fmaxf(a.z, 0.f); a.w = fmaxf(a.w, 0.f);
            *reinterpret_cast<float4*>(&hs[r4 + i][cg * 4]) = a;
        }
    }
    __syncthreads();

    // GEMM2: K=128 -> N=64, + b_at2, relu, dot w3
    {
        const int cg = tid & 15, rg = tid >> 4;
        const int r0 = rg * 2;
        float acc[2][4];
        #pragma unroll
        for (int i = 0; i < 2; i++)
            #pragma unroll
            for (int j = 0; j < 4; j++) acc[i][j] = 0.f;
        const float4* Wv = reinterpret_cast<const float4*>(W2);
        #pragma unroll 2
        for (int k0 = 0; k0 < 128; k0 += 4) {
            float4 xa0 = *reinterpret_cast<const float4*>(&hs[r0][k0]);
            float4 xa1 = *reinterpret_cast<const float4*>(&hs[r0 + 1][k0]);
            const float* x0 = reinterpret_cast<const float*>(&xa0);
            const float* x1 = reinterpret_cast<const float*>(&xa1);
            #pragma unroll
            for (int kk = 0; kk < 4; kk++) {
                float4 b = __ldg(Wv + (k0 + kk) * 16 + cg);
                float a0 = x0[kk], a1 = x1[kk];
                acc[0][0] = fmaf(a0, b.x, acc[0][0]);
                acc[0][1] = fmaf(a0, b.y, acc[0][1]);
                acc[0][2] = fmaf(a0, b.z, acc[0][2]);
                acc[0][3] = fmaf(a0, b.w, acc[0][3]);
                acc[1][0] = fmaf(a1, b.x, acc[1][0]);
                acc[1][1] = fmaf(a1, b.y, acc[1][1]);
                acc[1][2] = fmaf(a1, b.z, acc[1][2]);
                acc[1][3] = fmaf(a1, b.w, acc[1][3]);
            }
        }
        float4 bb = __ldg(reinterpret_cast<const float4*>(b2) + cg);
        float4 dw = __ldg(reinterpret_cast<const float4*>(w3) + cg);
        #pragma unroll
        for (int i = 0; i < 2; i++) {
            float4 a = make_float4(acc[i][0] + bb.x, acc[i][1] + bb.y,
                                   acc[i][2] + bb.z, acc[i][3] + bb.w);
            a.x = fmaxf(a.x, 0.f); a.y = fmaxf(a.y, 0.f);
            a.z = fmaxf(a.z, 0.f); a.w = fmaxf(a.w, 0.f);
            red[(r0 + i) * 16 + cg] = a.x * dw.x + a.y * dw.y + a.z * dw.z + a.w * dw.w;
        }
    }
    __syncthreads();
    if (tid < TP) {
        float s = 0.f;
        #pragma unroll
        for (int g = 0; g < 16; g++) s += red[tid * 16 + g];
        aq[pBase + tid] = s;
    }
}

// ---------------- imp3: fused act + 64->1 dot per pair + scalar sumsq ------
__global__ void __launch_bounds__(256) imp3f_k(
    const float* __restrict__ yi2,
    const float* __restrict__ wE, const float* __restrict__ wA,
    float* __restrict__ y3, double* __restrict__ ssd)
{
    constexpr int EBLK = PEc / 256;  // 400
    const int reg = (blockIdx.x >= EBLK) ? 1 : 0;
    const int pl = (blockIdx.x - reg * EBLK) * 256 + threadIdx.x;

    __shared__ float rcs[64];
    if (threadIdx.x < 64) {
        float m = (float)(ssd[(reg ? SS_IA2 : SS_IE2) + threadIdx.x] * (1.0 / REc));
        rcs[threadIdx.x] = __fsqrt_rn(__fadd_rn(m, EPS_));
    }
    __syncthreads();

    int gp = reg ? (PEc + pl) : pl;
    const float* src = yi2 + (size_t)(2 * gp) * 64;
    const float* w = reg ? wA : wE;

    float s0 = 0.f, s1 = 0.f;
    #pragma unroll
    for (int k4 = 0; k4 < 16; k4++) {
        float4 v0 = __ldg(reinterpret_cast<const float4*>(src) + k4);
        float4 v1 = __ldg(reinterpret_cast<const float4*>(src + 64) + k4);
        float4 dn = *reinterpret_cast<const float4*>(&rcs[k4 * 4]);
        float4 wv = __ldg(reinterpret_cast<const float4*>(w) + k4);
        #pragma unroll
        for (int j = 0; j < 4; j++) {
            float a = ((const float*)&v0)[j];
            float b = ((const float*)&v1)[j];
            actpair(a, b, ((const float*)&dn)[j]);
            float ww = ((const float*)&wv)[j];
            s0 = fmaf(a, ww, s0);
            s1 = fmaf(b, ww, s1);
        }
    }
    y3[2 * gp] = s0;
    y3[2 * gp + 1] = s1;

    __shared__ float red[256];
    red[threadIdx.x] = s0 * s0 + s1 * s1;
    __syncthreads();
    for (int o = 128; o > 0; o >>= 1) {
        if (threadIdx.x < o) red[threadIdx.x] += red[threadIdx.x + o];
        __syncthreads();
    }
    if (threadIdx.x == 0) atomicAdd(ssd + (reg ? SS_IA3 : SS_IE3), (double)red[0]);
}

// ---------------- move_vec accumulation ----------------
__global__ void mv_k(const float* __restrict__ y3, const double* __restrict__ ssd,
                     float* __restrict__ mv)
{
    int idx = blockIdx.x * blockDim.x + threadIdx.x;
    if (idx >= 2 * PEc) return;
    bool isE = idx < PEc;
    int p = isE ? idx : idx - PEc;
    float m = (float)(ssd[isE ? SS_IE3 : SS_IA3] * (1.0 / REc));
    float denom = __fsqrt_rn(__fadd_rn(m, EPS_));
    size_t base = (isE ? (size_t)0 : (size_t)REc) + (size_t)p * 2;
    float b0 = __fdiv_rn(y3[base], denom);
    float b1 = __fdiv_rn(y3[base + 1], denom);
    float mod = __fsqrt_rn(__fadd_rn(__fmul_rn(b0, b0), __fmul_rn(b1, b1)));
    float coeff = fminf(mod, 1.f);
    int agent = p / NE;
    atomicAdd(mv + agent * 2,     __fmul_rn(b0, coeff));
    atomicAdd(mv + agent * 2 + 1, __fmul_rn(b1, coeff));
}

// ---------------- final assembly ----------------
__device__ __forceinline__ float wred(float v) {
    #pragma unroll
    for (int o = 16; o; o >>= 1) v += __shfl_xor_sync(0xffffffffu, v, o);
    return v;
}

__global__ void __launch_bounds__(256) final_k(
    const float* __restrict__ oah, const float* __restrict__ Woa2,
    const float* __restrict__ boa2,
    const float* __restrict__ aqbuf, const float* __restrict__ bat3,
    const float* __restrict__ mv, float* __restrict__ out)
{
    int agent = blockIdx.x * 8 + (threadIdx.x >> 5);
    int lane = threadIdx.x & 31;
    const float* oa = oah + (size_t)agent * 64;
    float o0 = oa[2 * lane], o1 = oa[2 * lane + 1];
    float q[3];
    #pragma unroll
    for (int j = 0; j < 3; j++) {
        float part = o0 * __ldg(Woa2 + (2 * lane) * 3 + j)
                   + o1 * __ldg(Woa2 + (2 * lane + 1) * 3 + j);
        q[j] = wred(part);
    }
    float* o = out + (size_t)agent * 16;
    if (lane == 0) {
        float q2 = q[2] + boa2[2];
        float m0 = mv[agent * 2], m1 = mv[agent * 2 + 1];
        o[0] = q[0] + boa2[0];
        o[1] = q[1] + boa2[1];
        o[2] = q2 + m1;
        o[3] = q2 - m1;
        o[4] = q2 + m0;
        o[5] = q2 - m0;
    }
    if (lane < NE)
        o[6 + lane] = aqbuf[(size_t)agent * NE + lane] + bat3[0];
}

// ---------------- launcher ----------------
extern "C" void kernel_launch(void* const* d_in, const int* in_sizes, int n_in,
                              void* d_out, int out_size)
{
    const float* own   = (const float*)d_in[0];
    const float* ef    = (const float*)d_in[1];
    const float* af    = (const float*)d_in[2];
    const float* W_e1  = (const float*)d_in[3];
    const float* W_e2  = (const float*)d_in[4];
    const float* W_a1  = (const float*)d_in[5];
    const float* W_a2  = (const float*)d_in[6];
    const float* W_f1  = (const float*)d_in[7];
    const float* W_f2  = (const float*)d_in[8];
    const float* W_ie1 = (const float*)d_in[9];
    const float* W_ie2 = (const float*)d_in[10];
    const float* W_ie3 = (const float*)d_in[11];
    const float* W_ia1 = (const float*)d_in[12];
    const float* W_ia2 = (const float*)d_in[13];
    const float* W_ia3 = (const float*)d_in[14];
    const float* W_oa1 = (const float*)d_in[15];
    const float* b_oa1 = (const float*)d_in[16];
    const float* W_oa2 = (const float*)d_in[17];
    const float* b_oa2 = (const float*)d_in[18];
    const float* W_at1 = (const float*)d_in[19];
    const float* b_at1 = (const float*)d_in[20];
    const float* W_at2 = (const float*)d_in[21];
    const float* b_at2 = (const float*)d_in[22];
    const float* W_at3 = (const float*)d_in[23];
    const float* b_at3 = (const float*)d_in[24];
    float* out = (float*)d_out;

    float* S = nullptr;
    cudaGetSymbolAddress((void**)&S, g_scratch);
    double* ssd = nullptr;
    cudaGetSymbolAddress((void**)&ssd, g_ssd);

    // side stream + fork/join events (resources cached; work identical per call)
    static cudaStream_t s2 = nullptr;
    static cudaEvent_t eF = nullptr, eJ = nullptr;
    if (s2 == nullptr) {
        cudaStreamCreateWithFlags(&s2, cudaStreamNonBlocking);
        cudaEventCreateWithFlags(&eF, cudaEventDisableTiming);
        cudaEventCreateWithFlags(&eJ, cudaEventDisableTiming);
    }

    zero_k<<<80, 256>>>(S + OFF_MV, ssd);

    // layer 1 (ref-exact build_vec + W_e1/W_a1), raw output + ss E1/A1
    layer1_k<<<(PEc + PAc) / 32, 64>>>(own, ef, af, W_e1, W_a1, S + OFF_Y1, ssd);

    // layer 2, dual region, act(Y1) fused on load, ss E2/A2 (Y2 stays RAW)
    gemm_k<64, 64, 0, false, true, 1><<<RTc / 64, 256>>>(
        REc / 64,
        S + OFF_Y1, S + OFF_Y1 + (size_t)REc * 64,
        S + OFF_Y2, S + OFF_Y2 + (size_t)REc * 64,
        W_e2, W_a2, nullptr, nullptr,
        ssd + SS_E2, ssd + SS_A2,
        ssd + SS_E1, ssd + SS_A1, 1.0 / REc, 1.0 / RAc);

    // fused act + qmaxpool on raw Y2
    maxpoolf_k<<<(NAg * 64) / 256, 256>>>(S + OFF_Y2, S + OFF_Y2 + (size_t)REc * 64,
                                          ssd, S + OFF_POOL);
    gemm_k<64, 64, 0, false, true, 0><<<(2 * NAg) / 64, 256>>>(
        (2 * NAg) / 64, S + OFF_POOL, S + OFF_POOL, S + OFF_YF1, S + OFF_YF1,
        W_f1, W_f1, nullptr, nullptr, ssd + SS_F1, ssd + SS_F1,
        nullptr, nullptr, 0.0, 0.0);
    gemm_k<64, 64, 0, false, true, 1><<<(2 * NAg) / 64, 256>>>(
        (2 * NAg) / 64, S + OFF_YF1, S + OFF_YF1, S + OFF_VF, S + OFF_VF,
        W_f2, W_f2, nullptr, nullptr, ssd + SS_F2, ssd + SS_F2,
        ssd + SS_F1, ssd + SS_F1, 1.0 / (2 * NAg), 1.0 / (2 * NAg));
    act_k<<<(NAg * 64) / 256, 256>>>(S + OFF_VF, ssd + SS_F2, NAg, 1.0 / (2 * NAg), S + OFF_SF);

    // ---- fork: attention + oaq branch on s2, importance chain on default ----
    cudaEventRecord(eF, 0);
    cudaStreamWaitEvent(s2, eF, 0);

    // s2: oaq hidden
    gemm_k<64, 64, 1, true, false, 0><<<NAg / 64, 256, 0, s2>>>(
        NAg / 64, S + OFF_SF, S + OFF_SF, S + OFF_OAH, S + OFF_OAH,
        W_oa1, W_oa1, b_oa1, b_oa1, nullptr, nullptr,
        nullptr, nullptr, 0.0, 0.0);
    // s2: sf@W_at1_top + bias
    gemm_k<64, 128, 1, false, false, 0><<<NAg / 32, 256, 0, s2>>>(
        NAg / 32, S + OFF_SF, S + OFF_SF, S + OFF_SFC, S + OFF_SFC,
        W_at1, W_at1, b_at1, b_at1, nullptr, nullptr,
        nullptr, nullptr, 0.0, 0.0);
    // s2: fused attention (merge -> at1 -> at2 -> dot)
    attn_k<<<PEc / 32, 256, 0, s2>>>(
        S + OFF_Y2, W_at1 + 64 * 128, S + OFF_SFC,
        W_at2, b_at2, W_at3, S + OFF_AQ, ssd + SS_E2);
    cudaEventRecord(eJ, s2);

    // default: vf @ top-half of W_ie1 / W_ia1 (dual)
    gemm_k<64, 64, 0, false, false, 0><<<2 * ((2 * NAg) / 64), 256>>>(
        (2 * NAg) / 64, S + OFF_VF, S + OFF_VF, S + OFF_VCE, S + OFF_VCA,
        W_ie1, W_ia1, nullptr, nullptr, nullptr, nullptr,
        nullptr, nullptr, 0.0, 0.0);

    // importance layer 1: PAIRED kernel (one pass over raw Y2-E, act on load)
    gemmpair_k<<<REc / 32, 256>>>(
        S + OFF_Y2, W_ie1 + 64 * 64, W_ia1 + 64 * 64,
        S + OFF_VCE, S + OFF_VCA,
        S + OFF_YI1E, S + OFF_YI1A,
        ssd + SS_IE1, ssd + SS_IA1,
        ssd + SS_E2, 1.0 / REc);

    // importance layer 2 (dual, act fused on load), ss IE2/IA2
    gemm_k<64, 64, 0, false, true, 1><<<2 * (REc / 64), 256>>>(
        REc / 64, S + OFF_YI1E, S + OFF_YI1A, S + OFF_YI2E, S + OFF_YI2A,
        W_ie2, W_ia2, nullptr, nullptr,
        ssd + SS_IE2, ssd + SS_IA2,
        ssd + SS_IE1, ssd + SS_IA1, 1.0 / REc, 1.0 / REc);

    // importance layer 3 (act fused) + move vec — BOTH regions PEc pairs
    imp3f_k<<<2 * (PEc / 256), 256>>>(S + OFF_YI2E, W_ie3, W_ia3, S + OFF_Y3, ssd);
    mv_k<<<(2 * PEc + 255) / 256, 256>>>(S + OFF_Y3, ssd, S + OFF_MV);

    // ---- join ----
    cudaStreamWaitEvent(0, eJ, 0);
    final_k<<<NAg / 8, 256>>>(S + OFF_OAH, W_oa2, b_oa2, S + OFF_AQ, b_at3, S + OFF_MV, out);

    (void)in_sizes; (void)n_in; (void)out_size;
}